// round 13
// baseline (speedup 1.0000x reference)
#include <cuda_runtime.h>
#include <cuda_bf16.h>
#include <cuda_fp16.h>
#include <math.h>
#include <stdint.h>

// ---------------- dims ----------------
#define BB     8
#define TT     512
#define EE     64
#define HH     512
#define VV     32000
#define G3     1536
#define MM     4096        // B*T
#define KK     512
#define NCH    4096
#define CHUNK  16
#define NCHUNK 32

// ---------------- scratch (static device globals) ----------------
__device__ float g_buf[MM * G3];
__device__ float F_buf[NCHUNK * NCH];
__device__ float Gc_buf[NCHUNK * NCH];
__device__ float c0_buf[NCHUNK * NCH];

__device__ __nv_bfloat16 Ahi_buf[MM * KK];      // layer-1 activations (bf16 hi)
__device__ __nv_bfloat16 Alo_buf[MM * KK];      // layer-1 activations (bf16 lo)
__device__ __nv_bfloat16 B2hi_buf[G3 * KK];
__device__ __nv_bfloat16 B2lo_buf[G3 * KK];
__device__ __half A16_buf[MM * KK];             // layer-2 activations (fp16)
__device__ __half Bp16_buf[(size_t)VV * KK];    // Wp^T fp16

__device__ __forceinline__ float sigmoidf_(float x) {
    return 1.0f / (1.0f + expf(-x));
}

__device__ __forceinline__ uint32_t smem_u32(const void* p) {
    uint32_t a;
    asm("{ .reg .u64 t; cvta.to.shared.u64 t, %1; cvt.u32.u64 %0, t; }" : "=r"(a) : "l"(p));
    return a;
}
__device__ __forceinline__ void cp_async16(uint32_t s, const void* g) {
    asm volatile("cp.async.cg.shared.global [%0], [%1], 16;" :: "r"(s), "l"(g));
}
__device__ __forceinline__ void cp_commit() {
    asm volatile("cp.async.commit_group;");
}
template<int N>
__device__ __forceinline__ void cp_wait() {
    asm volatile("cp.async.wait_group %0;" :: "n"(N));
}
__device__ __forceinline__ void ldm_x4(uint32_t& r0, uint32_t& r1, uint32_t& r2, uint32_t& r3,
                                       uint32_t addr) {
    asm volatile("ldmatrix.sync.aligned.m8n8.x4.shared.b16 {%0,%1,%2,%3}, [%4];"
                 : "=r"(r0), "=r"(r1), "=r"(r2), "=r"(r3) : "r"(addr));
}
__device__ __forceinline__ void mma_bf16(float& c0, float& c1, float& c2, float& c3,
                                         uint32_t a0, uint32_t a1, uint32_t a2, uint32_t a3,
                                         uint32_t b0, uint32_t b1) {
    asm volatile("mma.sync.aligned.m16n8k16.row.col.f32.bf16.bf16.f32 "
                 "{%0,%1,%2,%3}, {%4,%5,%6,%7}, {%8,%9}, {%0,%1,%2,%3};"
                 : "+f"(c0), "+f"(c1), "+f"(c2), "+f"(c3)
                 : "r"(a0), "r"(a1), "r"(a2), "r"(a3), "r"(b0), "r"(b1));
}
__device__ __forceinline__ void mma_f16(float& c0, float& c1, float& c2, float& c3,
                                        uint32_t a0, uint32_t a1, uint32_t a2, uint32_t a3,
                                        uint32_t b0, uint32_t b1) {
    asm volatile("mma.sync.aligned.m16n8k16.row.col.f32.f16.f16.f32 "
                 "{%0,%1,%2,%3}, {%4,%5,%6,%7}, {%8,%9}, {%0,%1,%2,%3};"
                 : "+f"(c0), "+f"(c1), "+f"(c2), "+f"(c3)
                 : "r"(a0), "r"(a1), "r"(a2), "r"(a3), "r"(b0), "r"(b1));
}

// ---------------------------------------------------------------------------
// GEMM1: embed-gather fused small GEMM, K=64
// ---------------------------------------------------------------------------
__global__ __launch_bounds__(256) void gemm1_kernel(
    const int* __restrict__ inputs, const float* __restrict__ emb,
    const float* __restrict__ W1, const float* __restrict__ b1)
{
    __shared__ float Xs[64 * 65];
    __shared__ float Ws[64 * 64];
    __shared__ int   toks[64];

    const int tid = threadIdx.x;
    const int m0 = blockIdx.y * 64;
    const int n0 = blockIdx.x * 64;

    if (tid < 64) {
        int m = m0 + tid;
        int b = m & 7;
        int t = m >> 3;
        toks[tid] = inputs[b * TT + t];
    }
    __syncthreads();

    #pragma unroll
    for (int i = 0; i < 16; i++) {
        int lin = tid + i * 256;
        int row = lin >> 6, k = lin & 63;
        Xs[row * 65 + k] = emb[toks[row] * EE + k];
    }
    #pragma unroll
    for (int i = 0; i < 16; i++) {
        int lin = tid + i * 256;
        int k = lin >> 6, col = lin & 63;
        Ws[k * 64 + col] = W1[k * G3 + n0 + col];
    }
    __syncthreads();

    const int tx = tid & 15, ty = tid >> 4;
    float acc[4][4] = {};
    #pragma unroll
    for (int k = 0; k < 64; k++) {
        float a[4], w[4];
        #pragma unroll
        for (int i = 0; i < 4; i++) a[i] = Xs[(ty * 4 + i) * 65 + k];
        #pragma unroll
        for (int j = 0; j < 4; j++) w[j] = Ws[k * 64 + tx * 4 + j];
        #pragma unroll
        for (int i = 0; i < 4; i++)
            #pragma unroll
            for (int j = 0; j < 4; j++)
                acc[i][j] = fmaf(a[i], w[j], acc[i][j]);
    }

    #pragma unroll
    for (int i = 0; i < 4; i++) {
        int m = m0 + ty * 4 + i;
        #pragma unroll
        for (int j = 0; j < 4; j++) {
            int n = n0 + tx * 4 + j;
            float v = acc[i][j] + b1[n];
            v = (n < HH) ? tanhf(v) : sigmoidf_(v);
            g_buf[m * G3 + n] = v;
        }
    }
}

// ---------------------------------------------------------------------------
// fo-pool scan, 3 phases, float4-vectorized over h (4 channels/thread).
// Phase C layer 0 -> bf16 hi/lo (row t*B+b); layer 1 -> fp16 (row b*T+t)
// ---------------------------------------------------------------------------
__global__ __launch_bounds__(256) void scan_phaseA_kernel()
{
    const int ch4 = blockIdx.x * 256 + threadIdx.x;   // 0..1023
    const int chunk = blockIdx.y;
    const int b = ch4 >> 7;                           // (ch4*4)>>9
    const int h = (ch4 & 127) * 4;
    const int t0 = chunk * CHUNK;
    float4 c = make_float4(0.f, 0.f, 0.f, 0.f);
    float4 F = make_float4(1.f, 1.f, 1.f, 1.f);
    #pragma unroll
    for (int i = 0; i < CHUNK; i++) {
        int base = ((t0 + i) * BB + b) * G3 + h;
        float4 z = *(const float4*)&g_buf[base];
        float4 f = *(const float4*)&g_buf[base + HH];
        c.x = f.x * c.x + (1.0f - f.x) * z.x;  F.x *= f.x;
        c.y = f.y * c.y + (1.0f - f.y) * z.y;  F.y *= f.y;
        c.z = f.z * c.z + (1.0f - f.z) * z.z;  F.z *= f.z;
        c.w = f.w * c.w + (1.0f - f.w) * z.w;  F.w *= f.w;
    }
    *(float4*)&F_buf[chunk * NCH + ch4 * 4]  = F;
    *(float4*)&Gc_buf[chunk * NCH + ch4 * 4] = c;
}

__global__ __launch_bounds__(256) void scan_phaseB_kernel()
{
    const int ch4 = blockIdx.x * 256 + threadIdx.x;   // 0..1023
    float4 c = make_float4(0.f, 0.f, 0.f, 0.f);
    #pragma unroll
    for (int j = 0; j < NCHUNK; j++) {
        *(float4*)&c0_buf[j * NCH + ch4 * 4] = c;
        float4 F = *(const float4*)&F_buf[j * NCH + ch4 * 4];
        float4 G = *(const float4*)&Gc_buf[j * NCH + ch4 * 4];
        c.x = F.x * c.x + G.x;
        c.y = F.y * c.y + G.y;
        c.z = F.z * c.z + G.z;
        c.w = F.w * c.w + G.w;
    }
}

__global__ __launch_bounds__(256) void scan_phaseC_kernel(int layer)
{
    const int ch4 = blockIdx.x * 256 + threadIdx.x;
    const int chunk = blockIdx.y;
    const int b = ch4 >> 7;
    const int h = (ch4 & 127) * 4;
    const int t0 = chunk * CHUNK;
    float4 c = *(const float4*)&c0_buf[chunk * NCH + ch4 * 4];
    #pragma unroll
    for (int i = 0; i < CHUNK; i++) {
        int t = t0 + i;
        int base = (t * BB + b) * G3 + h;
        float4 z = *(const float4*)&g_buf[base];
        float4 f = *(const float4*)&g_buf[base + HH];
        float4 o = *(const float4*)&g_buf[base + 2 * HH];
        c.x = f.x * c.x + (1.0f - f.x) * z.x;
        c.y = f.y * c.y + (1.0f - f.y) * z.y;
        c.z = f.z * c.z + (1.0f - f.z) * z.z;
        c.w = f.w * c.w + (1.0f - f.w) * z.w;
        float v0 = o.x * c.x, v1 = o.y * c.y, v2 = o.z * c.z, v3 = o.w * c.w;
        if (layer == 0) {
            int idx = (t * BB + b) * HH + h;
            __nv_bfloat162 h01 = __floats2bfloat162_rn(v0, v1);
            __nv_bfloat162 h23 = __floats2bfloat162_rn(v2, v3);
            *(__nv_bfloat162*)(Ahi_buf + idx)     = h01;
            *(__nv_bfloat162*)(Ahi_buf + idx + 2) = h23;
            float r0 = v0 - __bfloat162float(h01.x);
            float r1 = v1 - __bfloat162float(h01.y);
            float r2 = v2 - __bfloat162float(h23.x);
            float r3 = v3 - __bfloat162float(h23.y);
            *(__nv_bfloat162*)(Alo_buf + idx)     = __floats2bfloat162_rn(r0, r1);
            *(__nv_bfloat162*)(Alo_buf + idx + 2) = __floats2bfloat162_rn(r2, r3);
        } else {
            int idx = (b * TT + t) * HH + h;
            *(__half2*)(A16_buf + idx)     = __floats2half2_rn(v0, v1);
            *(__half2*)(A16_buf + idx + 2) = __floats2half2_rn(v2, v3);
        }
    }
}

// ---------------------------------------------------------------------------
// W [K=512, N] -> B [N, K=512] transpose + split (bf16 hi/lo, for GEMM2)
// ---------------------------------------------------------------------------
__global__ __launch_bounds__(256) void transpose_split_kernel(
    const float* __restrict__ W, int N,
    __nv_bfloat16* __restrict__ Bhi, __nv_bfloat16* __restrict__ Blo)
{
    __shared__ float ts[32][33];
    const int n0 = blockIdx.x * 32;
    const int k0 = blockIdx.y * 32;
    const int tx = threadIdx.x, ty = threadIdx.y;

    #pragma unroll
    for (int i = 0; i < 4; i++)
        ts[ty + i * 8][tx] = W[(size_t)(k0 + ty + i * 8) * N + n0 + tx];
    __syncthreads();
    #pragma unroll
    for (int i = 0; i < 4; i++) {
        float x = ts[tx][ty + i * 8];
        __nv_bfloat16 h = __float2bfloat16_rn(x);
        float r = x - __bfloat162float(h);
        size_t o = (size_t)(n0 + ty + i * 8) * KK + k0 + tx;
        Bhi[o] = h;
        Blo[o] = __float2bfloat16_rn(r);
    }
}

// ---------------------------------------------------------------------------
// Wp [K=512, V] -> B [V, K=512] fp16 transpose, 64k x 32n tiles.
// Each warp writes one n-row of 64 fp16 = 128 B contiguous (half2 per lane).
// ---------------------------------------------------------------------------
__global__ __launch_bounds__(256) void transpose_f16_kernel(
    const float* __restrict__ W, int N, __half* __restrict__ Bo)
{
    __shared__ float ts[64][33];
    const int n0 = blockIdx.x * 32;
    const int k0 = blockIdx.y * 64;
    const int tid = threadIdx.x;
    const int lane = tid & 31;
    const int w = tid >> 5;

    #pragma unroll
    for (int i = 0; i < 8; i++) {
        int kr = w + i * 8;
        ts[kr][lane] = W[(size_t)(k0 + kr) * N + n0 + lane];
    }
    __syncthreads();
    #pragma unroll
    for (int p = 0; p < 4; p++) {
        int n = w * 4 + p;
        __half2 v = __floats2half2_rn(ts[2 * lane][n], ts[2 * lane + 1][n]);
        *(__half2*)(Bo + (size_t)(n0 + n) * KK + k0 + 2 * lane) = v;
    }
}

#define LDS_STRIDE 40          // bf16 elems per smem row, k32 tiles (32 + 8 pad)
#define TILE_BYTES 10240       // 128 rows * 80 B
#define EPI_STRIDE 132         // fp32 elems per epilogue smem row
#define EPI_BYTES  (128 * EPI_STRIDE * 4)   // 67584

// ---------------------------------------------------------------------------
// GEMM2: HMMA bf16 split, 3 passes fused per k-chunk (unchanged, ~70% eff)
// ---------------------------------------------------------------------------
#define STAGE3_BYTES (4 * TILE_BYTES)
#define TG3_SMEM (2 * STAGE3_BYTES)    // 81920 > EPI_BYTES

__global__ __launch_bounds__(128, 2) void tgemm3_kernel(
    const __nv_bfloat16* __restrict__ Ahi, const __nv_bfloat16* __restrict__ Alo,
    const __nv_bfloat16* __restrict__ Bhi, const __nv_bfloat16* __restrict__ Blo,
    const float* __restrict__ bias, float* __restrict__ C)
{
    extern __shared__ __nv_bfloat16 dsm[];
    const uint32_t sbase = smem_u32(dsm);

    const int tid  = threadIdx.x;
    const int wid  = tid >> 5;
    const int lane = tid & 31;
    const int m0 = blockIdx.y * 128;
    const int n0 = blockIdx.x * 128;
    const int wm = (wid & 1) * 64;
    const int wn = (wid >> 1) * 64;

    const int ldRow = tid >> 2;
    const int ldG   = tid & 3;

    float acc[4][8][4] = {};

    auto issue_loads = [&](int kc, int s) {
        const int k0 = kc * 32;
        const uint32_t st = sbase + s * STAGE3_BYTES;
        #pragma unroll
        for (int it = 0; it < 4; it++) {
            int row = ldRow + it * 32;
            uint32_t soff = (uint32_t)(row * LDS_STRIDE + ldG * 8) * 2;
            size_t ga = (size_t)(m0 + row) * KK + k0 + ldG * 8;
            size_t gb = (size_t)(n0 + row) * KK + k0 + ldG * 8;
            cp_async16(st + 0 * TILE_BYTES + soff, Ahi + ga);
            cp_async16(st + 1 * TILE_BYTES + soff, Alo + ga);
            cp_async16(st + 2 * TILE_BYTES + soff, Bhi + gb);
            cp_async16(st + 3 * TILE_BYTES + soff, Blo + gb);
        }
        cp_commit();
    };

    issue_loads(0, 0);

    for (int kc = 0; kc < 16; kc++) {
        const int s = kc & 1;
        cp_wait<0>();
        __syncthreads();
        if (kc + 1 < 16) issue_loads(kc + 1, s ^ 1);

        const uint32_t st = sbase + s * STAGE3_BYTES;
        const uint32_t sAhi = st;
        const uint32_t sAlo = st + 1 * TILE_BYTES;
        const uint32_t sBhi = st + 2 * TILE_BYTES;
        const uint32_t sBlo = st + 3 * TILE_BYTES;

        #pragma unroll
        for (int ks = 0; ks < 2; ks++) {
            const int kb = ks * 32;
            const uint32_t aoff = (uint32_t)((wm + (lane & 15)) * LDS_STRIDE) * 2
                                  + kb + ((lane >> 4) * 16);
            const uint32_t boff = (uint32_t)((wn + (lane & 7) + ((lane >> 4) & 1) * 8)
                                  * LDS_STRIDE) * 2 + kb + (((lane >> 3) & 1) * 16);

            uint32_t ahf[4][4], alf[4][4];
            uint32_t bhf[8][2], blf[8][2];
            #pragma unroll
            for (int mt = 0; mt < 4; mt++)
                ldm_x4(ahf[mt][0], ahf[mt][1], ahf[mt][2], ahf[mt][3],
                       sAhi + aoff + (uint32_t)(mt * 16 * LDS_STRIDE * 2));
            #pragma unroll
            for (int nt2 = 0; nt2 < 4; nt2++) {
                uint32_t r0, r1, r2, r3;
                ldm_x4(r0, r1, r2, r3, sBhi + boff + (uint32_t)(nt2 * 16 * LDS_STRIDE * 2));
                bhf[nt2 * 2 + 0][0] = r0; bhf[nt2 * 2 + 0][1] = r1;
                bhf[nt2 * 2 + 1][0] = r2; bhf[nt2 * 2 + 1][1] = r3;
            }
            #pragma unroll
            for (int nt2 = 0; nt2 < 4; nt2++) {
                uint32_t r0, r1, r2, r3;
                ldm_x4(r0, r1, r2, r3, sBlo + boff + (uint32_t)(nt2 * 16 * LDS_STRIDE * 2));
                blf[nt2 * 2 + 0][0] = r0; blf[nt2 * 2 + 0][1] = r1;
                blf[nt2 * 2 + 1][0] = r2; blf[nt2 * 2 + 1][1] = r3;
            }
            #pragma unroll
            for (int mt = 0; mt < 4; mt++)
                ldm_x4(alf[mt][0], alf[mt][1], alf[mt][2], alf[mt][3],
                       sAlo + aoff + (uint32_t)(mt * 16 * LDS_STRIDE * 2));

            #pragma unroll
            for (int mt = 0; mt < 4; mt++)
                #pragma unroll
                for (int nt = 0; nt < 8; nt++)
                    mma_bf16(acc[mt][nt][0], acc[mt][nt][1], acc[mt][nt][2], acc[mt][nt][3],
                             ahf[mt][0], ahf[mt][1], ahf[mt][2], ahf[mt][3],
                             bhf[nt][0], bhf[nt][1]);
            #pragma unroll
            for (int mt = 0; mt < 4; mt++)
                #pragma unroll
                for (int nt = 0; nt < 8; nt++)
                    mma_bf16(acc[mt][nt][0], acc[mt][nt][1], acc[mt][nt][2], acc[mt][nt][3],
                             ahf[mt][0], ahf[mt][1], ahf[mt][2], ahf[mt][3],
                             blf[nt][0], blf[nt][1]);
            #pragma unroll
            for (int mt = 0; mt < 4; mt++)
                #pragma unroll
                for (int nt = 0; nt < 8; nt++)
                    mma_bf16(acc[mt][nt][0], acc[mt][nt][1], acc[mt][nt][2], acc[mt][nt][3],
                             alf[mt][0], alf[mt][1], alf[mt][2], alf[mt][3],
                             bhf[nt][0], bhf[nt][1]);
        }
    }

    // Epilogue: bias + tanh/sigmoid -> SMEM -> coalesced float4 stores
    __syncthreads();
    float* cs = (float*)dsm;
    const int g = lane >> 2;
    const int cpair = (lane & 3) * 2;
    #pragma unroll
    for (int nt = 0; nt < 8; nt++) {
        int col = wn + nt * 8 + cpair;
        float bv0 = __ldg(bias + n0 + col);
        float bv1 = __ldg(bias + n0 + col + 1);
        #pragma unroll
        for (int mt = 0; mt < 4; mt++) {
            #pragma unroll
            for (int half = 0; half < 2; half++) {
                int row = wm + mt * 16 + g + half * 8;
                float x0 = acc[mt][nt][half * 2 + 0] + bv0;
                float x1 = acc[mt][nt][half * 2 + 1] + bv1;
                int n = n0 + col;
                x0 = (n < HH) ? tanhf(x0) : sigmoidf_(x0);
                x1 = (n + 1 < HH) ? tanhf(x1) : sigmoidf_(x1);
                cs[row * EPI_STRIDE + col]     = x0;
                cs[row * EPI_STRIDE + col + 1] = x1;
            }
        }
    }
    __syncthreads();
    #pragma unroll
    for (int i = 0; i < 32; i++) {
        int row = i * 4 + (tid >> 5);
        int col = (tid & 31) * 4;
        float4 v = *(float4*)&cs[row * EPI_STRIDE + col];
        *(float4*)&C[(size_t)(m0 + row) * G3 + n0 + col] = v;
    }
}

// ---------------------------------------------------------------------------
// Projection: single-pass fp16 HMMA, CTA 128x128, 4 warps of 64x64,
// K-chunk 64, 3-stage cp.async pipeline (prefetch distance 2 chunks
// ~2000 cyc of compute cover). 3 x 36864 B = 110592 B; 2 CTAs/SM (221 KB).
// ---------------------------------------------------------------------------
#define P_LDS_STRIDE 72                       // fp16 elems per row (64 + 8 pad)
#define P_TILE_BYTES (128 * 144)              // 18432
#define P_STAGE (2 * P_TILE_BYTES)            // A + B = 36864
#define TG1_SMEM (3 * P_STAGE)                // 110592 > EPI_BYTES

__global__ __launch_bounds__(128, 2) void tgemm1p_kernel(
    const __half* __restrict__ A16, const __half* __restrict__ B16,
    const float* __restrict__ bias, float* __restrict__ C)
{
    extern __shared__ __nv_bfloat16 dsm[];
    const uint32_t sbase = smem_u32(dsm);

    const int tid  = threadIdx.x;
    const int wid  = tid >> 5;
    const int lane = tid & 31;
    const int m0 = blockIdx.y * 128;
    const int n0 = blockIdx.x * 128;
    const int wm = (wid & 1) * 64;
    const int wn = (wid >> 1) * 64;

    const int ldRow = tid >> 3;            // 0..15
    const int ldG   = tid & 7;             // 16B chunk within 128B row

    float acc[4][8][4] = {};

    auto issue_loads = [&](int kc, int s) {
        const int k0 = kc * 64;
        const uint32_t sA = sbase + s * P_STAGE;
        const uint32_t sB = sA + P_TILE_BYTES;
        #pragma unroll
        for (int it = 0; it < 8; it++) {
            int row = ldRow + it * 16;
            uint32_t soff = (uint32_t)(row * P_LDS_STRIDE + ldG * 8) * 2;
            cp_async16(sA + soff, A16 + (size_t)(m0 + row) * KK + k0 + ldG * 8);
            cp_async16(sB + soff, B16 + (size_t)(n0 + row) * KK + k0 + ldG * 8);
        }
        cp_commit();
    };

    issue_loads(0, 0);
    issue_loads(1, 1);

    for (int kc = 0; kc < 8; kc++) {
        const int s = kc % 3;
        if (kc + 1 < 8) cp_wait<1>(); else cp_wait<0>();
        __syncthreads();
        if (kc + 2 < 8) issue_loads(kc + 2, (kc + 2) % 3);

        const uint32_t sA = sbase + s * P_STAGE;
        const uint32_t sB = sA + P_TILE_BYTES;

        #pragma unroll
        for (int ks = 0; ks < 4; ks++) {
            const int kb = ks * 32;        // byte offset of k16 step in 128B row
            const uint32_t aoff = (uint32_t)((wm + (lane & 15)) * P_LDS_STRIDE) * 2
                                  + kb + ((lane >> 4) * 16);
            const uint32_t boff = (uint32_t)((wn + (lane & 7) + ((lane >> 4) & 1) * 8)
                                  * P_LDS_STRIDE) * 2 + kb + (((lane >> 3) & 1) * 16);

            uint32_t af[4][4];
            uint32_t bf[8][2];
            #pragma unroll
            for (int mt = 0; mt < 4; mt++)
                ldm_x4(af[mt][0], af[mt][1], af[mt][2], af[mt][3],
                       sA + aoff + (uint32_t)(mt * 16 * P_LDS_STRIDE * 2));
            #pragma unroll
            for (int nt2 = 0; nt2 < 4; nt2++) {
                uint32_t r0, r1, r2, r3;
                ldm_x4(r0, r1, r2, r3, sB + boff + (uint32_t)(nt2 * 16 * P_LDS_STRIDE * 2));
                bf[nt2 * 2 + 0][0] = r0; bf[nt2 * 2 + 0][1] = r1;
                bf[nt2 * 2 + 1][0] = r2; bf[nt2 * 2 + 1][1] = r3;
            }

            #pragma unroll
            for (int mt = 0; mt < 4; mt++)
                #pragma unroll
                for (int nt = 0; nt < 8; nt++)
                    mma_f16(acc[mt][nt][0], acc[mt][nt][1], acc[mt][nt][2], acc[mt][nt][3],
                            af[mt][0], af[mt][1], af[mt][2], af[mt][3],
                            bf[nt][0], bf[nt][1]);
        }
    }

    // Epilogue: acc + bias -> SMEM -> coalesced float4 stores
    __syncthreads();
    float* cs = (float*)dsm;
    const int g = lane >> 2;
    const int cpair = (lane & 3) * 2;
    #pragma unroll
    for (int nt = 0; nt < 8; nt++) {
        int col = wn + nt * 8 + cpair;
        float bv0 = __ldg(bias + n0 + col);
        float bv1 = __ldg(bias + n0 + col + 1);
        #pragma unroll
        for (int mt = 0; mt < 4; mt++) {
            #pragma unroll
            for (int half = 0; half < 2; half++) {
                int row = wm + mt * 16 + g + half * 8;
                cs[row * EPI_STRIDE + col]     = acc[mt][nt][half * 2 + 0] + bv0;
                cs[row * EPI_STRIDE + col + 1] = acc[mt][nt][half * 2 + 1] + bv1;
            }
        }
    }
    __syncthreads();
    #pragma unroll
    for (int i = 0; i < 32; i++) {
        int row = i * 4 + (tid >> 5);
        int col = (tid & 31) * 4;
        float4 v = *(float4*)&cs[row * EPI_STRIDE + col];
        *(float4*)&C[(size_t)(m0 + row) * VV + n0 + col] = v;
    }
}

// ---------------------------------------------------------------------------
// Launch
// ---------------------------------------------------------------------------
extern "C" void kernel_launch(void* const* d_in, const int* in_sizes, int n_in,
                              void* d_out, int out_size)
{
    const int*   inputs = (const int*)d_in[0];
    const float* emb    = (const float*)d_in[1];
    const float* W1     = (const float*)d_in[2];
    const float* b1     = (const float*)d_in[3];
    const float* W2     = (const float*)d_in[4];
    const float* b2     = (const float*)d_in[5];
    const float* Wp     = (const float*)d_in[6];
    const float* bp     = (const float*)d_in[7];
    float* out = (float*)d_out;

    cudaFuncSetAttribute(tgemm3_kernel,
                         cudaFuncAttributeMaxDynamicSharedMemorySize, TG3_SMEM);
    cudaFuncSetAttribute(tgemm1p_kernel,
                         cudaFuncAttributeMaxDynamicSharedMemorySize, TG1_SMEM);

    float* g_gbuf;
    __nv_bfloat16 *g_Ahi, *g_Alo, *g_B2hi, *g_B2lo;
    __half *g_A16, *g_Bp16;
    cudaGetSymbolAddress((void**)&g_gbuf, g_buf);
    cudaGetSymbolAddress((void**)&g_Ahi,  Ahi_buf);
    cudaGetSymbolAddress((void**)&g_Alo,  Alo_buf);
    cudaGetSymbolAddress((void**)&g_B2hi, B2hi_buf);
    cudaGetSymbolAddress((void**)&g_B2lo, B2lo_buf);
    cudaGetSymbolAddress((void**)&g_A16,  A16_buf);
    cudaGetSymbolAddress((void**)&g_Bp16, Bp16_buf);

    // Weight prep (independent of activations)
    transpose_split_kernel<<<dim3(G3 / 32, KK / 32), dim3(32, 8)>>>(W2, G3, g_B2hi, g_B2lo);
    transpose_f16_kernel<<<dim3(VV / 32, KK / 64), 256>>>(Wp, VV, g_Bp16);

    // Layer 1: embed + GEMM1 + activations -> g_buf
    gemm1_kernel<<<dim3(G3 / 64, MM / 64), 256>>>(inputs, emb, W1, b1);

    // Layer 1 fo-pool -> bf16 hi/lo (rows t*B+b)
    scan_phaseA_kernel<<<dim3(4, NCHUNK), 256>>>();
    scan_phaseB_kernel<<<4, 256>>>();
    scan_phaseC_kernel<<<dim3(4, NCHUNK), 256>>>(0);

    // Layer 2: 3-pass bf16 GEMM -> g_buf with activations
    tgemm3_kernel<<<dim3(G3 / 128, MM / 128), 128, TG3_SMEM>>>(
        g_Ahi, g_Alo, g_B2hi, g_B2lo, b2, g_gbuf);

    // Layer 2 fo-pool -> fp16 (rows b*T+t)
    scan_phaseA_kernel<<<dim3(4, NCHUNK), 256>>>();
    scan_phaseB_kernel<<<4, 256>>>();
    scan_phaseC_kernel<<<dim3(4, NCHUNK), 256>>>(1);

    // Projection: single-pass fp16 GEMM, k64 chunks, 3-stage pipeline -> out
    tgemm1p_kernel<<<dim3(VV / 128, MM / 128), 128, TG1_SMEM>>>(
        g_A16, g_Bp16, bp, out);
}

// round 14
// speedup vs baseline: 1.0223x; 1.0223x over previous
#include <cuda_runtime.h>
#include <cuda_bf16.h>
#include <cuda_fp16.h>
#include <math.h>
#include <stdint.h>

// ---------------- dims ----------------
#define BB     8
#define TT     512
#define EE     64
#define HH     512
#define VV     32000
#define G3     1536
#define MM     4096        // B*T
#define KK     512
#define NCH    4096
#define CHUNK  16
#define NCHUNK 32

// ---------------- scratch (static device globals) ----------------
__device__ __half g_buf[MM * G3];               // pre-pool z/f/o, fp16
__device__ float F_buf[NCHUNK * NCH];
__device__ float Gc_buf[NCHUNK * NCH];
__device__ float c0_buf[NCHUNK * NCH];

__device__ __nv_bfloat16 Ahi_buf[MM * KK];      // layer-1 activations (bf16 hi)
__device__ __nv_bfloat16 Alo_buf[MM * KK];      // layer-1 activations (bf16 lo)
__device__ __nv_bfloat16 B2hi_buf[G3 * KK];
__device__ __nv_bfloat16 B2lo_buf[G3 * KK];
__device__ __half A16_buf[MM * KK];             // layer-2 activations (fp16)
__device__ __half Bp16_buf[(size_t)VV * KK];    // Wp^T fp16

__device__ __forceinline__ float sigmoidf_(float x) {
    return 1.0f / (1.0f + expf(-x));
}

__device__ __forceinline__ uint32_t smem_u32(const void* p) {
    uint32_t a;
    asm("{ .reg .u64 t; cvta.to.shared.u64 t, %1; cvt.u32.u64 %0, t; }" : "=r"(a) : "l"(p));
    return a;
}
__device__ __forceinline__ void cp_async16(uint32_t s, const void* g) {
    asm volatile("cp.async.cg.shared.global [%0], [%1], 16;" :: "r"(s), "l"(g));
}
__device__ __forceinline__ void cp_commit() {
    asm volatile("cp.async.commit_group;");
}
template<int N>
__device__ __forceinline__ void cp_wait() {
    asm volatile("cp.async.wait_group %0;" :: "n"(N));
}
__device__ __forceinline__ void ldm_x4(uint32_t& r0, uint32_t& r1, uint32_t& r2, uint32_t& r3,
                                       uint32_t addr) {
    asm volatile("ldmatrix.sync.aligned.m8n8.x4.shared.b16 {%0,%1,%2,%3}, [%4];"
                 : "=r"(r0), "=r"(r1), "=r"(r2), "=r"(r3) : "r"(addr));
}
__device__ __forceinline__ void mma_bf16(float& c0, float& c1, float& c2, float& c3,
                                         uint32_t a0, uint32_t a1, uint32_t a2, uint32_t a3,
                                         uint32_t b0, uint32_t b1) {
    asm volatile("mma.sync.aligned.m16n8k16.row.col.f32.bf16.bf16.f32 "
                 "{%0,%1,%2,%3}, {%4,%5,%6,%7}, {%8,%9}, {%0,%1,%2,%3};"
                 : "+f"(c0), "+f"(c1), "+f"(c2), "+f"(c3)
                 : "r"(a0), "r"(a1), "r"(a2), "r"(a3), "r"(b0), "r"(b1));
}
__device__ __forceinline__ void mma_f16(float& c0, float& c1, float& c2, float& c3,
                                        uint32_t a0, uint32_t a1, uint32_t a2, uint32_t a3,
                                        uint32_t b0, uint32_t b1) {
    asm volatile("mma.sync.aligned.m16n8k16.row.col.f32.f16.f16.f32 "
                 "{%0,%1,%2,%3}, {%4,%5,%6,%7}, {%8,%9}, {%0,%1,%2,%3};"
                 : "+f"(c0), "+f"(c1), "+f"(c2), "+f"(c3)
                 : "r"(a0), "r"(a1), "r"(a2), "r"(a3), "r"(b0), "r"(b1));
}

// ---------------------------------------------------------------------------
// GEMM1: embed-gather fused small GEMM, K=64. Output fp16 z/f/o.
// ---------------------------------------------------------------------------
__global__ __launch_bounds__(256) void gemm1_kernel(
    const int* __restrict__ inputs, const float* __restrict__ emb,
    const float* __restrict__ W1, const float* __restrict__ b1)
{
    __shared__ float Xs[64 * 65];
    __shared__ float Ws[64 * 64];
    __shared__ int   toks[64];

    const int tid = threadIdx.x;
    const int m0 = blockIdx.y * 64;
    const int n0 = blockIdx.x * 64;

    if (tid < 64) {
        int m = m0 + tid;
        int b = m & 7;
        int t = m >> 3;
        toks[tid] = inputs[b * TT + t];
    }
    __syncthreads();

    #pragma unroll
    for (int i = 0; i < 16; i++) {
        int lin = tid + i * 256;
        int row = lin >> 6, k = lin & 63;
        Xs[row * 65 + k] = emb[toks[row] * EE + k];
    }
    #pragma unroll
    for (int i = 0; i < 16; i++) {
        int lin = tid + i * 256;
        int k = lin >> 6, col = lin & 63;
        Ws[k * 64 + col] = W1[k * G3 + n0 + col];
    }
    __syncthreads();

    const int tx = tid & 15, ty = tid >> 4;
    float acc[4][4] = {};
    #pragma unroll
    for (int k = 0; k < 64; k++) {
        float a[4], w[4];
        #pragma unroll
        for (int i = 0; i < 4; i++) a[i] = Xs[(ty * 4 + i) * 65 + k];
        #pragma unroll
        for (int j = 0; j < 4; j++) w[j] = Ws[k * 64 + tx * 4 + j];
        #pragma unroll
        for (int i = 0; i < 4; i++)
            #pragma unroll
            for (int j = 0; j < 4; j++)
                acc[i][j] = fmaf(a[i], w[j], acc[i][j]);
    }

    #pragma unroll
    for (int i = 0; i < 4; i++) {
        int m = m0 + ty * 4 + i;
        float v[4];
        #pragma unroll
        for (int j = 0; j < 4; j++) {
            int n = n0 + tx * 4 + j;
            float x = acc[i][j] + b1[n];
            v[j] = (n < HH) ? tanhf(x) : sigmoidf_(x);
        }
        __half2 p0 = __floats2half2_rn(v[0], v[1]);
        __half2 p1 = __floats2half2_rn(v[2], v[3]);
        *(__half2*)(g_buf + (size_t)m * G3 + n0 + tx * 4)     = p0;
        *(__half2*)(g_buf + (size_t)m * G3 + n0 + tx * 4 + 2) = p1;
    }
}

// ---------------------------------------------------------------------------
// fo-pool scan, 3 phases, half2 inputs, 2 channels/thread (grid 8x32).
// Phase C layer 0 -> bf16 hi/lo (row t*B+b); layer 1 -> fp16 (row b*T+t)
// ---------------------------------------------------------------------------
__global__ __launch_bounds__(256) void scan_phaseA_kernel()
{
    const int ch2 = blockIdx.x * 256 + threadIdx.x;   // 0..2047
    const int chunk = blockIdx.y;
    const int b = ch2 >> 8;
    const int h = (ch2 & 255) * 2;
    const int t0 = chunk * CHUNK;
    float2 c = make_float2(0.f, 0.f);
    float2 F = make_float2(1.f, 1.f);
    #pragma unroll
    for (int i = 0; i < CHUNK; i++) {
        int base = ((t0 + i) * BB + b) * G3 + h;
        float2 z = __half22float2(*(const __half2*)&g_buf[base]);
        float2 f = __half22float2(*(const __half2*)&g_buf[base + HH]);
        c.x = f.x * c.x + (1.0f - f.x) * z.x;  F.x *= f.x;
        c.y = f.y * c.y + (1.0f - f.y) * z.y;  F.y *= f.y;
    }
    *(float2*)&F_buf[chunk * NCH + ch2 * 2]  = F;
    *(float2*)&Gc_buf[chunk * NCH + ch2 * 2] = c;
}

__global__ __launch_bounds__(256) void scan_phaseB_kernel()
{
    const int ch2 = blockIdx.x * 256 + threadIdx.x;   // 0..2047
    float2 c = make_float2(0.f, 0.f);
    #pragma unroll
    for (int j = 0; j < NCHUNK; j++) {
        *(float2*)&c0_buf[j * NCH + ch2 * 2] = c;
        float2 F = *(const float2*)&F_buf[j * NCH + ch2 * 2];
        float2 G = *(const float2*)&Gc_buf[j * NCH + ch2 * 2];
        c.x = F.x * c.x + G.x;
        c.y = F.y * c.y + G.y;
    }
}

__global__ __launch_bounds__(256) void scan_phaseC_kernel(int layer)
{
    const int ch2 = blockIdx.x * 256 + threadIdx.x;
    const int chunk = blockIdx.y;
    const int b = ch2 >> 8;
    const int h = (ch2 & 255) * 2;
    const int t0 = chunk * CHUNK;
    float2 c = *(const float2*)&c0_buf[chunk * NCH + ch2 * 2];
    #pragma unroll
    for (int i = 0; i < CHUNK; i++) {
        int t = t0 + i;
        int base = (t * BB + b) * G3 + h;
        float2 z = __half22float2(*(const __half2*)&g_buf[base]);
        float2 f = __half22float2(*(const __half2*)&g_buf[base + HH]);
        float2 o = __half22float2(*(const __half2*)&g_buf[base + 2 * HH]);
        c.x = f.x * c.x + (1.0f - f.x) * z.x;
        c.y = f.y * c.y + (1.0f - f.y) * z.y;
        float v0 = o.x * c.x, v1 = o.y * c.y;
        if (layer == 0) {
            int idx = (t * BB + b) * HH + h;
            __nv_bfloat162 hi = __floats2bfloat162_rn(v0, v1);
            *(__nv_bfloat162*)(Ahi_buf + idx) = hi;
            float r0 = v0 - __bfloat162float(hi.x);
            float r1 = v1 - __bfloat162float(hi.y);
            *(__nv_bfloat162*)(Alo_buf + idx) = __floats2bfloat162_rn(r0, r1);
        } else {
            int idx = (b * TT + t) * HH + h;
            *(__half2*)(A16_buf + idx) = __floats2half2_rn(v0, v1);
        }
    }
}

// ---------------------------------------------------------------------------
// W [K=512, N] -> B [N, K=512] transpose + split (bf16 hi/lo, for GEMM2)
// ---------------------------------------------------------------------------
__global__ __launch_bounds__(256) void transpose_split_kernel(
    const float* __restrict__ W, int N,
    __nv_bfloat16* __restrict__ Bhi, __nv_bfloat16* __restrict__ Blo)
{
    __shared__ float ts[32][33];
    const int n0 = blockIdx.x * 32;
    const int k0 = blockIdx.y * 32;
    const int tx = threadIdx.x, ty = threadIdx.y;

    #pragma unroll
    for (int i = 0; i < 4; i++)
        ts[ty + i * 8][tx] = W[(size_t)(k0 + ty + i * 8) * N + n0 + tx];
    __syncthreads();
    #pragma unroll
    for (int i = 0; i < 4; i++) {
        float x = ts[tx][ty + i * 8];
        __nv_bfloat16 h = __float2bfloat16_rn(x);
        float r = x - __bfloat162float(h);
        size_t o = (size_t)(n0 + ty + i * 8) * KK + k0 + tx;
        Bhi[o] = h;
        Blo[o] = __float2bfloat16_rn(r);
    }
}

// ---------------------------------------------------------------------------
// Wp [K=512, V] -> B [V, K=512] fp16 transpose, 64k x 32n tiles.
// ---------------------------------------------------------------------------
__global__ __launch_bounds__(256) void transpose_f16_kernel(
    const float* __restrict__ W, int N, __half* __restrict__ Bo)
{
    __shared__ float ts[64][33];
    const int n0 = blockIdx.x * 32;
    const int k0 = blockIdx.y * 64;
    const int tid = threadIdx.x;
    const int lane = tid & 31;
    const int w = tid >> 5;

    #pragma unroll
    for (int i = 0; i < 8; i++) {
        int kr = w + i * 8;
        ts[kr][lane] = W[(size_t)(k0 + kr) * N + n0 + lane];
    }
    __syncthreads();
    #pragma unroll
    for (int p = 0; p < 4; p++) {
        int n = w * 4 + p;
        __half2 v = __floats2half2_rn(ts[2 * lane][n], ts[2 * lane + 1][n]);
        *(__half2*)(Bo + (size_t)(n0 + n) * KK + k0 + 2 * lane) = v;
    }
}

#define LDS_STRIDE 40          // bf16 elems per smem row, k32 tiles (32 + 8 pad)
#define TILE_BYTES 10240       // 128 rows * 80 B
#define EPI_STRIDE 132         // fp32 elems per epilogue smem row
#define EPI_BYTES  (128 * EPI_STRIDE * 4)   // 67584

// ---------------------------------------------------------------------------
// GEMM2: HMMA bf16 split, 3 passes fused per k-chunk; fp16 z/f/o output.
// ---------------------------------------------------------------------------
#define STAGE3_BYTES (4 * TILE_BYTES)
#define TG3_SMEM (2 * STAGE3_BYTES)    // 81920 > EPI_BYTES

__global__ __launch_bounds__(128, 2) void tgemm3_kernel(
    const __nv_bfloat16* __restrict__ Ahi, const __nv_bfloat16* __restrict__ Alo,
    const __nv_bfloat16* __restrict__ Bhi, const __nv_bfloat16* __restrict__ Blo,
    const float* __restrict__ bias, __half* __restrict__ C)
{
    extern __shared__ __nv_bfloat16 dsm[];
    const uint32_t sbase = smem_u32(dsm);

    const int tid  = threadIdx.x;
    const int wid  = tid >> 5;
    const int lane = tid & 31;
    const int m0 = blockIdx.y * 128;
    const int n0 = blockIdx.x * 128;
    const int wm = (wid & 1) * 64;
    const int wn = (wid >> 1) * 64;

    const int ldRow = tid >> 2;
    const int ldG   = tid & 3;

    float acc[4][8][4] = {};

    auto issue_loads = [&](int kc, int s) {
        const int k0 = kc * 32;
        const uint32_t st = sbase + s * STAGE3_BYTES;
        #pragma unroll
        for (int it = 0; it < 4; it++) {
            int row = ldRow + it * 32;
            uint32_t soff = (uint32_t)(row * LDS_STRIDE + ldG * 8) * 2;
            size_t ga = (size_t)(m0 + row) * KK + k0 + ldG * 8;
            size_t gb = (size_t)(n0 + row) * KK + k0 + ldG * 8;
            cp_async16(st + 0 * TILE_BYTES + soff, Ahi + ga);
            cp_async16(st + 1 * TILE_BYTES + soff, Alo + ga);
            cp_async16(st + 2 * TILE_BYTES + soff, Bhi + gb);
            cp_async16(st + 3 * TILE_BYTES + soff, Blo + gb);
        }
        cp_commit();
    };

    issue_loads(0, 0);

    for (int kc = 0; kc < 16; kc++) {
        const int s = kc & 1;
        cp_wait<0>();
        __syncthreads();
        if (kc + 1 < 16) issue_loads(kc + 1, s ^ 1);

        const uint32_t st = sbase + s * STAGE3_BYTES;
        const uint32_t sAhi = st;
        const uint32_t sAlo = st + 1 * TILE_BYTES;
        const uint32_t sBhi = st + 2 * TILE_BYTES;
        const uint32_t sBlo = st + 3 * TILE_BYTES;

        #pragma unroll
        for (int ks = 0; ks < 2; ks++) {
            const int kb = ks * 32;
            const uint32_t aoff = (uint32_t)((wm + (lane & 15)) * LDS_STRIDE) * 2
                                  + kb + ((lane >> 4) * 16);
            const uint32_t boff = (uint32_t)((wn + (lane & 7) + ((lane >> 4) & 1) * 8)
                                  * LDS_STRIDE) * 2 + kb + (((lane >> 3) & 1) * 16);

            uint32_t ahf[4][4], alf[4][4];
            uint32_t bhf[8][2], blf[8][2];
            #pragma unroll
            for (int mt = 0; mt < 4; mt++)
                ldm_x4(ahf[mt][0], ahf[mt][1], ahf[mt][2], ahf[mt][3],
                       sAhi + aoff + (uint32_t)(mt * 16 * LDS_STRIDE * 2));
            #pragma unroll
            for (int nt2 = 0; nt2 < 4; nt2++) {
                uint32_t r0, r1, r2, r3;
                ldm_x4(r0, r1, r2, r3, sBhi + boff + (uint32_t)(nt2 * 16 * LDS_STRIDE * 2));
                bhf[nt2 * 2 + 0][0] = r0; bhf[nt2 * 2 + 0][1] = r1;
                bhf[nt2 * 2 + 1][0] = r2; bhf[nt2 * 2 + 1][1] = r3;
            }
            #pragma unroll
            for (int nt2 = 0; nt2 < 4; nt2++) {
                uint32_t r0, r1, r2, r3;
                ldm_x4(r0, r1, r2, r3, sBlo + boff + (uint32_t)(nt2 * 16 * LDS_STRIDE * 2));
                blf[nt2 * 2 + 0][0] = r0; blf[nt2 * 2 + 0][1] = r1;
                blf[nt2 * 2 + 1][0] = r2; blf[nt2 * 2 + 1][1] = r3;
            }
            #pragma unroll
            for (int mt = 0; mt < 4; mt++)
                ldm_x4(alf[mt][0], alf[mt][1], alf[mt][2], alf[mt][3],
                       sAlo + aoff + (uint32_t)(mt * 16 * LDS_STRIDE * 2));

            #pragma unroll
            for (int mt = 0; mt < 4; mt++)
                #pragma unroll
                for (int nt = 0; nt < 8; nt++)
                    mma_bf16(acc[mt][nt][0], acc[mt][nt][1], acc[mt][nt][2], acc[mt][nt][3],
                             ahf[mt][0], ahf[mt][1], ahf[mt][2], ahf[mt][3],
                             bhf[nt][0], bhf[nt][1]);
            #pragma unroll
            for (int mt = 0; mt < 4; mt++)
                #pragma unroll
                for (int nt = 0; nt < 8; nt++)
                    mma_bf16(acc[mt][nt][0], acc[mt][nt][1], acc[mt][nt][2], acc[mt][nt][3],
                             ahf[mt][0], ahf[mt][1], ahf[mt][2], ahf[mt][3],
                             blf[nt][0], blf[nt][1]);
            #pragma unroll
            for (int mt = 0; mt < 4; mt++)
                #pragma unroll
                for (int nt = 0; nt < 8; nt++)
                    mma_bf16(acc[mt][nt][0], acc[mt][nt][1], acc[mt][nt][2], acc[mt][nt][3],
                             alf[mt][0], alf[mt][1], alf[mt][2], alf[mt][3],
                             bhf[nt][0], bhf[nt][1]);
        }
    }

    // Epilogue: bias + tanh/sigmoid -> SMEM fp32 -> fp16 8B coalesced stores
    __syncthreads();
    float* cs = (float*)dsm;
    const int g = lane >> 2;
    const int cpair = (lane & 3) * 2;
    #pragma unroll
    for (int nt = 0; nt < 8; nt++) {
        int col = wn + nt * 8 + cpair;
        float bv0 = __ldg(bias + n0 + col);
        float bv1 = __ldg(bias + n0 + col + 1);
        #pragma unroll
        for (int mt = 0; mt < 4; mt++) {
            #pragma unroll
            for (int half = 0; half < 2; half++) {
                int row = wm + mt * 16 + g + half * 8;
                float x0 = acc[mt][nt][half * 2 + 0] + bv0;
                float x1 = acc[mt][nt][half * 2 + 1] + bv1;
                int n = n0 + col;
                x0 = (n < HH) ? tanhf(x0) : sigmoidf_(x0);
                x1 = (n + 1 < HH) ? tanhf(x1) : sigmoidf_(x1);
                cs[row * EPI_STRIDE + col]     = x0;
                cs[row * EPI_STRIDE + col + 1] = x1;
            }
        }
    }
    __syncthreads();
    #pragma unroll
    for (int i = 0; i < 32; i++) {
        int row = i * 4 + (tid >> 5);
        int col = (tid & 31) * 4;
        float4 v = *(float4*)&cs[row * EPI_STRIDE + col];
        __half2 p0 = __floats2half2_rn(v.x, v.y);
        __half2 p1 = __floats2half2_rn(v.z, v.w);
        __half2* dst = (__half2*)(C + (size_t)(m0 + row) * G3 + n0 + col);
        dst[0] = p0;
        dst[1] = p1;
    }
}

// ---------------------------------------------------------------------------
// Projection: single-pass fp16 HMMA, CTA 128x128, 4 warps of 64x64,
// K-chunk 64, 3-stage cp.async pipeline (unchanged from R13).
// ---------------------------------------------------------------------------
#define P_LDS_STRIDE 72                       // fp16 elems per row (64 + 8 pad)
#define P_TILE_BYTES (128 * 144)              // 18432
#define P_STAGE (2 * P_TILE_BYTES)            // A + B = 36864
#define TG1_SMEM (3 * P_STAGE)                // 110592 > EPI_BYTES

__global__ __launch_bounds__(128, 2) void tgemm1p_kernel(
    const __half* __restrict__ A16, const __half* __restrict__ B16,
    const float* __restrict__ bias, float* __restrict__ C)
{
    extern __shared__ __nv_bfloat16 dsm[];
    const uint32_t sbase = smem_u32(dsm);

    const int tid  = threadIdx.x;
    const int wid  = tid >> 5;
    const int lane = tid & 31;
    const int m0 = blockIdx.y * 128;
    const int n0 = blockIdx.x * 128;
    const int wm = (wid & 1) * 64;
    const int wn = (wid >> 1) * 64;

    const int ldRow = tid >> 3;            // 0..15
    const int ldG   = tid & 7;             // 16B chunk within 128B row

    float acc[4][8][4] = {};

    auto issue_loads = [&](int kc, int s) {
        const int k0 = kc * 64;
        const uint32_t sA = sbase + s * P_STAGE;
        const uint32_t sB = sA + P_TILE_BYTES;
        #pragma unroll
        for (int it = 0; it < 8; it++) {
            int row = ldRow + it * 16;
            uint32_t soff = (uint32_t)(row * P_LDS_STRIDE + ldG * 8) * 2;
            cp_async16(sA + soff, A16 + (size_t)(m0 + row) * KK + k0 + ldG * 8);
            cp_async16(sB + soff, B16 + (size_t)(n0 + row) * KK + k0 + ldG * 8);
        }
        cp_commit();
    };

    issue_loads(0, 0);
    issue_loads(1, 1);

    for (int kc = 0; kc < 8; kc++) {
        const int s = kc % 3;
        if (kc + 1 < 8) cp_wait<1>(); else cp_wait<0>();
        __syncthreads();
        if (kc + 2 < 8) issue_loads(kc + 2, (kc + 2) % 3);

        const uint32_t sA = sbase + s * P_STAGE;
        const uint32_t sB = sA + P_TILE_BYTES;

        #pragma unroll
        for (int ks = 0; ks < 4; ks++) {
            const int kb = ks * 32;
            const uint32_t aoff = (uint32_t)((wm + (lane & 15)) * P_LDS_STRIDE) * 2
                                  + kb + ((lane >> 4) * 16);
            const uint32_t boff = (uint32_t)((wn + (lane & 7) + ((lane >> 4) & 1) * 8)
                                  * P_LDS_STRIDE) * 2 + kb + (((lane >> 3) & 1) * 16);

            uint32_t af[4][4];
            uint32_t bf[8][2];
            #pragma unroll
            for (int mt = 0; mt < 4; mt++)
                ldm_x4(af[mt][0], af[mt][1], af[mt][2], af[mt][3],
                       sA + aoff + (uint32_t)(mt * 16 * P_LDS_STRIDE * 2));
            #pragma unroll
            for (int nt2 = 0; nt2 < 4; nt2++) {
                uint32_t r0, r1, r2, r3;
                ldm_x4(r0, r1, r2, r3, sB + boff + (uint32_t)(nt2 * 16 * P_LDS_STRIDE * 2));
                bf[nt2 * 2 + 0][0] = r0; bf[nt2 * 2 + 0][1] = r1;
                bf[nt2 * 2 + 1][0] = r2; bf[nt2 * 2 + 1][1] = r3;
            }

            #pragma unroll
            for (int mt = 0; mt < 4; mt++)
                #pragma unroll
                for (int nt = 0; nt < 8; nt++)
                    mma_f16(acc[mt][nt][0], acc[mt][nt][1], acc[mt][nt][2], acc[mt][nt][3],
                            af[mt][0], af[mt][1], af[mt][2], af[mt][3],
                            bf[nt][0], bf[nt][1]);
        }
    }

    // Epilogue: acc + bias -> SMEM -> coalesced float4 stores
    __syncthreads();
    float* cs = (float*)dsm;
    const int g = lane >> 2;
    const int cpair = (lane & 3) * 2;
    #pragma unroll
    for (int nt = 0; nt < 8; nt++) {
        int col = wn + nt * 8 + cpair;
        float bv0 = __ldg(bias + n0 + col);
        float bv1 = __ldg(bias + n0 + col + 1);
        #pragma unroll
        for (int mt = 0; mt < 4; mt++) {
            #pragma unroll
            for (int half = 0; half < 2; half++) {
                int row = wm + mt * 16 + g + half * 8;
                cs[row * EPI_STRIDE + col]     = acc[mt][nt][half * 2 + 0] + bv0;
                cs[row * EPI_STRIDE + col + 1] = acc[mt][nt][half * 2 + 1] + bv1;
            }
        }
    }
    __syncthreads();
    #pragma unroll
    for (int i = 0; i < 32; i++) {
        int row = i * 4 + (tid >> 5);
        int col = (tid & 31) * 4;
        float4 v = *(float4*)&cs[row * EPI_STRIDE + col];
        *(float4*)&C[(size_t)(m0 + row) * VV + n0 + col] = v;
    }
}

// ---------------------------------------------------------------------------
// Launch
// ---------------------------------------------------------------------------
extern "C" void kernel_launch(void* const* d_in, const int* in_sizes, int n_in,
                              void* d_out, int out_size)
{
    const int*   inputs = (const int*)d_in[0];
    const float* emb    = (const float*)d_in[1];
    const float* W1     = (const float*)d_in[2];
    const float* b1     = (const float*)d_in[3];
    const float* W2     = (const float*)d_in[4];
    const float* b2     = (const float*)d_in[5];
    const float* Wp     = (const float*)d_in[6];
    const float* bp     = (const float*)d_in[7];
    float* out = (float*)d_out;

    cudaFuncSetAttribute(tgemm3_kernel,
                         cudaFuncAttributeMaxDynamicSharedMemorySize, TG3_SMEM);
    cudaFuncSetAttribute(tgemm1p_kernel,
                         cudaFuncAttributeMaxDynamicSharedMemorySize, TG1_SMEM);

    __half* g_gbuf;
    __nv_bfloat16 *g_Ahi, *g_Alo, *g_B2hi, *g_B2lo;
    __half *g_A16, *g_Bp16;
    cudaGetSymbolAddress((void**)&g_gbuf, g_buf);
    cudaGetSymbolAddress((void**)&g_Ahi,  Ahi_buf);
    cudaGetSymbolAddress((void**)&g_Alo,  Alo_buf);
    cudaGetSymbolAddress((void**)&g_B2hi, B2hi_buf);
    cudaGetSymbolAddress((void**)&g_B2lo, B2lo_buf);
    cudaGetSymbolAddress((void**)&g_A16,  A16_buf);
    cudaGetSymbolAddress((void**)&g_Bp16, Bp16_buf);

    // Weight prep (independent of activations)
    transpose_split_kernel<<<dim3(G3 / 32, KK / 32), dim3(32, 8)>>>(W2, G3, g_B2hi, g_B2lo);
    transpose_f16_kernel<<<dim3(VV / 32, KK / 64), 256>>>(Wp, VV, g_Bp16);

    // Layer 1: embed + GEMM1 + activations -> g_buf (fp16)
    gemm1_kernel<<<dim3(G3 / 64, MM / 64), 256>>>(inputs, emb, W1, b1);

    // Layer 1 fo-pool -> bf16 hi/lo (rows t*B+b)
    scan_phaseA_kernel<<<dim3(8, NCHUNK), 256>>>();
    scan_phaseB_kernel<<<8, 256>>>();
    scan_phaseC_kernel<<<dim3(8, NCHUNK), 256>>>(0);

    // Layer 2: 3-pass bf16 GEMM -> g_buf (fp16) with activations
    tgemm3_kernel<<<dim3(G3 / 128, MM / 128), 128, TG3_SMEM>>>(
        g_Ahi, g_Alo, g_B2hi, g_B2lo, b2, g_gbuf);

    // Layer 2 fo-pool -> fp16 (rows b*T+t)
    scan_phaseA_kernel<<<dim3(8, NCHUNK), 256>>>();
    scan_phaseB_kernel<<<8, 256>>>();
    scan_phaseC_kernel<<<dim3(8, NCHUNK), 256>>>(1);

    // Projection: single-pass fp16 GEMM, k64 chunks, 3-stage pipeline -> out
    tgemm1p_kernel<<<dim3(VV / 128, MM / 128), 128, TG1_SMEM>>>(
        g_A16, g_Bp16, bp, out);
}

// round 15
// speedup vs baseline: 1.0800x; 1.0564x over previous
#include <cuda_runtime.h>
#include <cuda_bf16.h>
#include <cuda_fp16.h>
#include <math.h>
#include <stdint.h>

// ---------------- dims ----------------
#define BB     8
#define TT     512
#define EE     64
#define HH     512
#define VV     32000
#define G3     1536
#define MM     4096        // B*T
#define KK     512
#define NCH    4096
#define CHUNK  16
#define NCHUNK 32

// ---------------- scratch (static device globals) ----------------
__device__ __half g_buf[MM * G3];               // pre-pool z/f/o, fp16
__device__ float F_buf[NCHUNK * NCH];
__device__ float Gc_buf[NCHUNK * NCH];
__device__ float c0_buf[NCHUNK * NCH];

__device__ __half A16_buf[MM * KK];             // scan outputs (both layers, fp16)
__device__ __half B216_buf[G3 * KK];            // W2^T fp16
__device__ __half Bp16_buf[(size_t)VV * KK];    // Wp^T fp16

__device__ __forceinline__ float sigmoidf_(float x) {
    return 1.0f / (1.0f + expf(-x));
}

__device__ __forceinline__ uint32_t smem_u32(const void* p) {
    uint32_t a;
    asm("{ .reg .u64 t; cvta.to.shared.u64 t, %1; cvt.u32.u64 %0, t; }" : "=r"(a) : "l"(p));
    return a;
}
__device__ __forceinline__ void cp_async16(uint32_t s, const void* g) {
    asm volatile("cp.async.cg.shared.global [%0], [%1], 16;" :: "r"(s), "l"(g));
}
__device__ __forceinline__ void cp_commit() {
    asm volatile("cp.async.commit_group;");
}
template<int N>
__device__ __forceinline__ void cp_wait() {
    asm volatile("cp.async.wait_group %0;" :: "n"(N));
}
__device__ __forceinline__ void ldm_x4(uint32_t& r0, uint32_t& r1, uint32_t& r2, uint32_t& r3,
                                       uint32_t addr) {
    asm volatile("ldmatrix.sync.aligned.m8n8.x4.shared.b16 {%0,%1,%2,%3}, [%4];"
                 : "=r"(r0), "=r"(r1), "=r"(r2), "=r"(r3) : "r"(addr));
}
__device__ __forceinline__ void mma_f16(float& c0, float& c1, float& c2, float& c3,
                                        uint32_t a0, uint32_t a1, uint32_t a2, uint32_t a3,
                                        uint32_t b0, uint32_t b1) {
    asm volatile("mma.sync.aligned.m16n8k16.row.col.f32.f16.f16.f32 "
                 "{%0,%1,%2,%3}, {%4,%5,%6,%7}, {%8,%9}, {%0,%1,%2,%3};"
                 : "+f"(c0), "+f"(c1), "+f"(c2), "+f"(c3)
                 : "r"(a0), "r"(a1), "r"(a2), "r"(a3), "r"(b0), "r"(b1));
}

// ---------------------------------------------------------------------------
// GEMM1: embed-gather fused small GEMM, K=64. Output fp16 z/f/o.
// ---------------------------------------------------------------------------
__global__ __launch_bounds__(256) void gemm1_kernel(
    const int* __restrict__ inputs, const float* __restrict__ emb,
    const float* __restrict__ W1, const float* __restrict__ b1)
{
    __shared__ float Xs[64 * 65];
    __shared__ float Ws[64 * 64];
    __shared__ int   toks[64];

    const int tid = threadIdx.x;
    const int m0 = blockIdx.y * 64;
    const int n0 = blockIdx.x * 64;

    if (tid < 64) {
        int m = m0 + tid;
        int b = m & 7;
        int t = m >> 3;
        toks[tid] = inputs[b * TT + t];
    }
    __syncthreads();

    #pragma unroll
    for (int i = 0; i < 16; i++) {
        int lin = tid + i * 256;
        int row = lin >> 6, k = lin & 63;
        Xs[row * 65 + k] = emb[toks[row] * EE + k];
    }
    #pragma unroll
    for (int i = 0; i < 16; i++) {
        int lin = tid + i * 256;
        int k = lin >> 6, col = lin & 63;
        Ws[k * 64 + col] = W1[k * G3 + n0 + col];
    }
    __syncthreads();

    const int tx = tid & 15, ty = tid >> 4;
    float acc[4][4] = {};
    #pragma unroll
    for (int k = 0; k < 64; k++) {
        float a[4], w[4];
        #pragma unroll
        for (int i = 0; i < 4; i++) a[i] = Xs[(ty * 4 + i) * 65 + k];
        #pragma unroll
        for (int j = 0; j < 4; j++) w[j] = Ws[k * 64 + tx * 4 + j];
        #pragma unroll
        for (int i = 0; i < 4; i++)
            #pragma unroll
            for (int j = 0; j < 4; j++)
                acc[i][j] = fmaf(a[i], w[j], acc[i][j]);
    }

    #pragma unroll
    for (int i = 0; i < 4; i++) {
        int m = m0 + ty * 4 + i;
        float v[4];
        #pragma unroll
        for (int j = 0; j < 4; j++) {
            int n = n0 + tx * 4 + j;
            float x = acc[i][j] + b1[n];
            v[j] = (n < HH) ? tanhf(x) : sigmoidf_(x);
        }
        __half2 p0 = __floats2half2_rn(v[0], v[1]);
        __half2 p1 = __floats2half2_rn(v[2], v[3]);
        *(__half2*)(g_buf + (size_t)m * G3 + n0 + tx * 4)     = p0;
        *(__half2*)(g_buf + (size_t)m * G3 + n0 + tx * 4 + 2) = p1;
    }
}

// ---------------------------------------------------------------------------
// fo-pool scan, 3 phases, half2 inputs, 2 channels/thread (grid 8x32).
// Phase C -> fp16 A16_buf (layer 0: row t*B+b; layer 1: row b*T+t)
// ---------------------------------------------------------------------------
__global__ __launch_bounds__(256) void scan_phaseA_kernel()
{
    const int ch2 = blockIdx.x * 256 + threadIdx.x;   // 0..2047
    const int chunk = blockIdx.y;
    const int b = ch2 >> 8;
    const int h = (ch2 & 255) * 2;
    const int t0 = chunk * CHUNK;
    float2 c = make_float2(0.f, 0.f);
    float2 F = make_float2(1.f, 1.f);
    #pragma unroll
    for (int i = 0; i < CHUNK; i++) {
        int base = ((t0 + i) * BB + b) * G3 + h;
        float2 z = __half22float2(*(const __half2*)&g_buf[base]);
        float2 f = __half22float2(*(const __half2*)&g_buf[base + HH]);
        c.x = f.x * c.x + (1.0f - f.x) * z.x;  F.x *= f.x;
        c.y = f.y * c.y + (1.0f - f.y) * z.y;  F.y *= f.y;
    }
    *(float2*)&F_buf[chunk * NCH + ch2 * 2]  = F;
    *(float2*)&Gc_buf[chunk * NCH + ch2 * 2] = c;
}

__global__ __launch_bounds__(256) void scan_phaseB_kernel()
{
    const int ch2 = blockIdx.x * 256 + threadIdx.x;   // 0..2047
    float2 c = make_float2(0.f, 0.f);
    #pragma unroll
    for (int j = 0; j < NCHUNK; j++) {
        *(float2*)&c0_buf[j * NCH + ch2 * 2] = c;
        float2 F = *(const float2*)&F_buf[j * NCH + ch2 * 2];
        float2 G = *(const float2*)&Gc_buf[j * NCH + ch2 * 2];
        c.x = F.x * c.x + G.x;
        c.y = F.y * c.y + G.y;
    }
}

__global__ __launch_bounds__(256) void scan_phaseC_kernel(int layer)
{
    const int ch2 = blockIdx.x * 256 + threadIdx.x;
    const int chunk = blockIdx.y;
    const int b = ch2 >> 8;
    const int h = (ch2 & 255) * 2;
    const int t0 = chunk * CHUNK;
    float2 c = *(const float2*)&c0_buf[chunk * NCH + ch2 * 2];
    #pragma unroll
    for (int i = 0; i < CHUNK; i++) {
        int t = t0 + i;
        int base = (t * BB + b) * G3 + h;
        float2 z = __half22float2(*(const __half2*)&g_buf[base]);
        float2 f = __half22float2(*(const __half2*)&g_buf[base + HH]);
        float2 o = __half22float2(*(const __half2*)&g_buf[base + 2 * HH]);
        c.x = f.x * c.x + (1.0f - f.x) * z.x;
        c.y = f.y * c.y + (1.0f - f.y) * z.y;
        float v0 = o.x * c.x, v1 = o.y * c.y;
        int idx = (layer == 0) ? ((t * BB + b) * HH + h) : ((b * TT + t) * HH + h);
        *(__half2*)(A16_buf + idx) = __floats2half2_rn(v0, v1);
    }
}

// ---------------------------------------------------------------------------
// W [K=512, N] -> B [N, K=512] fp16 transpose, 64k x 32n tiles.
// Each warp writes one n-row of 64 fp16 = 128 B contiguous (half2 per lane).
// ---------------------------------------------------------------------------
__global__ __launch_bounds__(256) void transpose_f16_kernel(
    const float* __restrict__ W, int N, __half* __restrict__ Bo)
{
    __shared__ float ts[64][33];
    const int n0 = blockIdx.x * 32;
    const int k0 = blockIdx.y * 64;
    const int tid = threadIdx.x;
    const int lane = tid & 31;
    const int w = tid >> 5;

    #pragma unroll
    for (int i = 0; i < 8; i++) {
        int kr = w + i * 8;
        ts[kr][lane] = W[(size_t)(k0 + kr) * N + n0 + lane];
    }
    __syncthreads();
    #pragma unroll
    for (int p = 0; p < 4; p++) {
        int n = w * 4 + p;
        __half2 v = __floats2half2_rn(ts[2 * lane][n], ts[2 * lane + 1][n]);
        *(__half2*)(Bo + (size_t)(n0 + n) * KK + k0 + 2 * lane) = v;
    }
}

// ---------------------------------------------------------------------------
// Unified single-pass fp16 HMMA GEMM: C[M,N] = A[M,512]*B[N,512]^T + bias.
// CTA 128x128, 4 warps of 64x64, K-chunk 64, 3-stage cp.async pipeline.
// ACT=1: tanh/sigmoid epilogue; OUT16=1: fp16 output, else fp32.
// ---------------------------------------------------------------------------
#define EPI_STRIDE 132                        // fp32 elems per epilogue smem row
#define P_LDS_STRIDE 72                       // fp16 elems per row (64 + 8 pad)
#define P_TILE_BYTES (128 * 144)              // 18432
#define P_STAGE (2 * P_TILE_BYTES)            // A + B = 36864
#define TG_SMEM (3 * P_STAGE)                 // 110592 > 128*132*4

template<int NGLOB, int ACT, int OUT16>
__global__ __launch_bounds__(128, 2) void tgemm_f16_kernel(
    const __half* __restrict__ A16, const __half* __restrict__ B16,
    const float* __restrict__ bias, void* __restrict__ Cv)
{
    extern __shared__ __nv_bfloat16 dsm[];
    const uint32_t sbase = smem_u32(dsm);

    const int tid  = threadIdx.x;
    const int wid  = tid >> 5;
    const int lane = tid & 31;
    const int m0 = blockIdx.y * 128;
    const int n0 = blockIdx.x * 128;
    const int wm = (wid & 1) * 64;
    const int wn = (wid >> 1) * 64;

    const int ldRow = tid >> 3;            // 0..15
    const int ldG   = tid & 7;             // 16B chunk within 128B row

    float acc[4][8][4] = {};

    auto issue_loads = [&](int kc, int s) {
        const int k0 = kc * 64;
        const uint32_t sA = sbase + s * P_STAGE;
        const uint32_t sB = sA + P_TILE_BYTES;
        #pragma unroll
        for (int it = 0; it < 8; it++) {
            int row = ldRow + it * 16;
            uint32_t soff = (uint32_t)(row * P_LDS_STRIDE + ldG * 8) * 2;
            cp_async16(sA + soff, A16 + (size_t)(m0 + row) * KK + k0 + ldG * 8);
            cp_async16(sB + soff, B16 + (size_t)(n0 + row) * KK + k0 + ldG * 8);
        }
        cp_commit();
    };

    issue_loads(0, 0);
    issue_loads(1, 1);

    for (int kc = 0; kc < 8; kc++) {
        const int s = kc % 3;
        if (kc + 1 < 8) cp_wait<1>(); else cp_wait<0>();
        __syncthreads();
        if (kc + 2 < 8) issue_loads(kc + 2, (kc + 2) % 3);

        const uint32_t sA = sbase + s * P_STAGE;
        const uint32_t sB = sA + P_TILE_BYTES;

        #pragma unroll
        for (int ks = 0; ks < 4; ks++) {
            const int kb = ks * 32;
            const uint32_t aoff = (uint32_t)((wm + (lane & 15)) * P_LDS_STRIDE) * 2
                                  + kb + ((lane >> 4) * 16);
            const uint32_t boff = (uint32_t)((wn + (lane & 7) + ((lane >> 4) & 1) * 8)
                                  * P_LDS_STRIDE) * 2 + kb + (((lane >> 3) & 1) * 16);

            uint32_t af[4][4];
            uint32_t bf[8][2];
            #pragma unroll
            for (int mt = 0; mt < 4; mt++)
                ldm_x4(af[mt][0], af[mt][1], af[mt][2], af[mt][3],
                       sA + aoff + (uint32_t)(mt * 16 * P_LDS_STRIDE * 2));
            #pragma unroll
            for (int nt2 = 0; nt2 < 4; nt2++) {
                uint32_t r0, r1, r2, r3;
                ldm_x4(r0, r1, r2, r3, sB + boff + (uint32_t)(nt2 * 16 * P_LDS_STRIDE * 2));
                bf[nt2 * 2 + 0][0] = r0; bf[nt2 * 2 + 0][1] = r1;
                bf[nt2 * 2 + 1][0] = r2; bf[nt2 * 2 + 1][1] = r3;
            }

            #pragma unroll
            for (int mt = 0; mt < 4; mt++)
                #pragma unroll
                for (int nt = 0; nt < 8; nt++)
                    mma_f16(acc[mt][nt][0], acc[mt][nt][1], acc[mt][nt][2], acc[mt][nt][3],
                            af[mt][0], af[mt][1], af[mt][2], af[mt][3],
                            bf[nt][0], bf[nt][1]);
        }
    }

    // Epilogue: bias (+ act) -> SMEM fp32 -> coalesced stores (fp16 or fp32)
    __syncthreads();
    float* cs = (float*)dsm;
    const int g = lane >> 2;
    const int cpair = (lane & 3) * 2;
    #pragma unroll
    for (int nt = 0; nt < 8; nt++) {
        int col = wn + nt * 8 + cpair;
        float bv0 = __ldg(bias + n0 + col);
        float bv1 = __ldg(bias + n0 + col + 1);
        #pragma unroll
        for (int mt = 0; mt < 4; mt++) {
            #pragma unroll
            for (int half = 0; half < 2; half++) {
                int row = wm + mt * 16 + g + half * 8;
                float x0 = acc[mt][nt][half * 2 + 0] + bv0;
                float x1 = acc[mt][nt][half * 2 + 1] + bv1;
                if (ACT) {
                    int n = n0 + col;
                    x0 = (n < HH) ? tanhf(x0) : sigmoidf_(x0);
                    x1 = (n + 1 < HH) ? tanhf(x1) : sigmoidf_(x1);
                }
                cs[row * EPI_STRIDE + col]     = x0;
                cs[row * EPI_STRIDE + col + 1] = x1;
            }
        }
    }
    __syncthreads();
    #pragma unroll
    for (int i = 0; i < 32; i++) {
        int row = i * 4 + (tid >> 5);
        int col = (tid & 31) * 4;
        float4 v = *(float4*)&cs[row * EPI_STRIDE + col];
        if (OUT16) {
            __half2 p0 = __floats2half2_rn(v.x, v.y);
            __half2 p1 = __floats2half2_rn(v.z, v.w);
            __half2* dst = (__half2*)((__half*)Cv + (size_t)(m0 + row) * NGLOB + n0 + col);
            dst[0] = p0;
            dst[1] = p1;
        } else {
            *(float4*)((float*)Cv + (size_t)(m0 + row) * NGLOB + n0 + col) = v;
        }
    }
}

// ---------------------------------------------------------------------------
// Launch
// ---------------------------------------------------------------------------
extern "C" void kernel_launch(void* const* d_in, const int* in_sizes, int n_in,
                              void* d_out, int out_size)
{
    const int*   inputs = (const int*)d_in[0];
    const float* emb    = (const float*)d_in[1];
    const float* W1     = (const float*)d_in[2];
    const float* b1     = (const float*)d_in[3];
    const float* W2     = (const float*)d_in[4];
    const float* b2     = (const float*)d_in[5];
    const float* Wp     = (const float*)d_in[6];
    const float* bp     = (const float*)d_in[7];
    float* out = (float*)d_out;

    cudaFuncSetAttribute(tgemm_f16_kernel<G3, 1, 1>,
                         cudaFuncAttributeMaxDynamicSharedMemorySize, TG_SMEM);
    cudaFuncSetAttribute(tgemm_f16_kernel<VV, 0, 0>,
                         cudaFuncAttributeMaxDynamicSharedMemorySize, TG_SMEM);

    __half *g_gbuf, *g_A16, *g_B216, *g_Bp16;
    cudaGetSymbolAddress((void**)&g_gbuf, g_buf);
    cudaGetSymbolAddress((void**)&g_A16,  A16_buf);
    cudaGetSymbolAddress((void**)&g_B216, B216_buf);
    cudaGetSymbolAddress((void**)&g_Bp16, Bp16_buf);

    // Weight prep (independent of activations)
    transpose_f16_kernel<<<dim3(G3 / 32, KK / 64), 256>>>(W2, G3, g_B216);
    transpose_f16_kernel<<<dim3(VV / 32, KK / 64), 256>>>(Wp, VV, g_Bp16);

    // Layer 1: embed + GEMM1 + activations -> g_buf (fp16)
    gemm1_kernel<<<dim3(G3 / 64, MM / 64), 256>>>(inputs, emb, W1, b1);

    // Layer 1 fo-pool -> A16_buf (rows t*B+b)
    scan_phaseA_kernel<<<dim3(8, NCHUNK), 256>>>();
    scan_phaseB_kernel<<<8, 256>>>();
    scan_phaseC_kernel<<<dim3(8, NCHUNK), 256>>>(0);

    // Layer 2: single-pass fp16 GEMM -> g_buf (fp16) with activations
    tgemm_f16_kernel<G3, 1, 1><<<dim3(G3 / 128, MM / 128), 128, TG_SMEM>>>(
        g_A16, g_B216, b2, g_gbuf);

    // Layer 2 fo-pool -> A16_buf (rows b*T+t)
    scan_phaseA_kernel<<<dim3(8, NCHUNK), 256>>>();
    scan_phaseB_kernel<<<8, 256>>>();
    scan_phaseC_kernel<<<dim3(8, NCHUNK), 256>>>(1);

    // Projection: single-pass fp16 GEMM -> out (fp32)
    tgemm_f16_kernel<VV, 0, 0><<<dim3(VV / 128, MM / 128), 128, TG_SMEM>>>(
        g_A16, g_Bp16, bp, out);
}

// round 16
// speedup vs baseline: 1.1064x; 1.0245x over previous
#include <cuda_runtime.h>
#include <cuda_bf16.h>
#include <cuda_fp16.h>
#include <math.h>
#include <stdint.h>

// ---------------- dims ----------------
#define BB     8
#define TT     512
#define EE     64
#define HH     512
#define VV     32000
#define G3     1536
#define MM     4096        // B*T
#define KK     512
#define NCH    4096
#define CHUNK  16
#define NCHUNK 32

// ---------------- scratch (static device globals) ----------------
__device__ __half g_buf[MM * G3];               // pre-pool z/f/o, fp16
__device__ float F_buf[NCHUNK * NCH];
__device__ float Gc_buf[NCHUNK * NCH];

__device__ __half A16_buf[MM * KK];             // scan outputs (both layers, fp16)
__device__ __half B216_buf[G3 * KK];            // W2^T fp16
__device__ __half Bp16_buf[(size_t)VV * KK];    // Wp^T fp16

__device__ __forceinline__ float sigmoidf_(float x) {
    return 1.0f / (1.0f + expf(-x));
}

__device__ __forceinline__ uint32_t smem_u32(const void* p) {
    uint32_t a;
    asm("{ .reg .u64 t; cvta.to.shared.u64 t, %1; cvt.u32.u64 %0, t; }" : "=r"(a) : "l"(p));
    return a;
}
__device__ __forceinline__ void cp_async16(uint32_t s, const void* g) {
    asm volatile("cp.async.cg.shared.global [%0], [%1], 16;" :: "r"(s), "l"(g));
}
__device__ __forceinline__ void cp_commit() {
    asm volatile("cp.async.commit_group;");
}
template<int N>
__device__ __forceinline__ void cp_wait() {
    asm volatile("cp.async.wait_group %0;" :: "n"(N));
}
__device__ __forceinline__ void ldm_x4(uint32_t& r0, uint32_t& r1, uint32_t& r2, uint32_t& r3,
                                       uint32_t addr) {
    asm volatile("ldmatrix.sync.aligned.m8n8.x4.shared.b16 {%0,%1,%2,%3}, [%4];"
                 : "=r"(r0), "=r"(r1), "=r"(r2), "=r"(r3) : "r"(addr));
}
__device__ __forceinline__ void mma_f16(float& c0, float& c1, float& c2, float& c3,
                                        uint32_t a0, uint32_t a1, uint32_t a2, uint32_t a3,
                                        uint32_t b0, uint32_t b1) {
    asm volatile("mma.sync.aligned.m16n8k16.row.col.f32.f16.f16.f32 "
                 "{%0,%1,%2,%3}, {%4,%5,%6,%7}, {%8,%9}, {%0,%1,%2,%3};"
                 : "+f"(c0), "+f"(c1), "+f"(c2), "+f"(c3)
                 : "r"(a0), "r"(a1), "r"(a2), "r"(a3), "r"(b0), "r"(b1));
}

// ---------------------------------------------------------------------------
// GEMM1: embed-gather fused small GEMM, K=64. Output fp16 z/f/o.
// ---------------------------------------------------------------------------
__global__ __launch_bounds__(256) void gemm1_kernel(
    const int* __restrict__ inputs, const float* __restrict__ emb,
    const float* __restrict__ W1, const float* __restrict__ b1)
{
    __shared__ float Xs[64 * 65];
    __shared__ float Ws[64 * 64];
    __shared__ int   toks[64];

    const int tid = threadIdx.x;
    const int m0 = blockIdx.y * 64;
    const int n0 = blockIdx.x * 64;

    if (tid < 64) {
        int m = m0 + tid;
        int b = m & 7;
        int t = m >> 3;
        toks[tid] = inputs[b * TT + t];
    }
    __syncthreads();

    #pragma unroll
    for (int i = 0; i < 16; i++) {
        int lin = tid + i * 256;
        int row = lin >> 6, k = lin & 63;
        Xs[row * 65 + k] = emb[toks[row] * EE + k];
    }
    #pragma unroll
    for (int i = 0; i < 16; i++) {
        int lin = tid + i * 256;
        int k = lin >> 6, col = lin & 63;
        Ws[k * 64 + col] = W1[k * G3 + n0 + col];
    }
    __syncthreads();

    const int tx = tid & 15, ty = tid >> 4;
    float acc[4][4] = {};
    #pragma unroll
    for (int k = 0; k < 64; k++) {
        float a[4], w[4];
        #pragma unroll
        for (int i = 0; i < 4; i++) a[i] = Xs[(ty * 4 + i) * 65 + k];
        #pragma unroll
        for (int j = 0; j < 4; j++) w[j] = Ws[k * 64 + tx * 4 + j];
        #pragma unroll
        for (int i = 0; i < 4; i++)
            #pragma unroll
            for (int j = 0; j < 4; j++)
                acc[i][j] = fmaf(a[i], w[j], acc[i][j]);
    }

    #pragma unroll
    for (int i = 0; i < 4; i++) {
        int m = m0 + ty * 4 + i;
        float v[4];
        #pragma unroll
        for (int j = 0; j < 4; j++) {
            int n = n0 + tx * 4 + j;
            float x = acc[i][j] + b1[n];
            v[j] = (n < HH) ? tanhf(x) : sigmoidf_(x);
        }
        __half2 p0 = __floats2half2_rn(v[0], v[1]);
        __half2 p1 = __floats2half2_rn(v[2], v[3]);
        *(__half2*)(g_buf + (size_t)m * G3 + n0 + tx * 4)     = p0;
        *(__half2*)(g_buf + (size_t)m * G3 + n0 + tx * 4 + 2) = p1;
    }
}

// ---------------------------------------------------------------------------
// fo-pool scan, 2 phases, half2 inputs, 2 channels/thread (grid 8x32).
// Phase A: per-chunk (F, G). Phase C: recompute chunk prefix from (F, G)
// (<=31 dependent fmas), then replay chunk and emit fp16 activations.
// ---------------------------------------------------------------------------
__global__ __launch_bounds__(256) void scan_phaseA_kernel()
{
    const int ch2 = blockIdx.x * 256 + threadIdx.x;   // 0..2047
    const int chunk = blockIdx.y;
    const int b = ch2 >> 8;
    const int h = (ch2 & 255) * 2;
    const int t0 = chunk * CHUNK;
    float2 c = make_float2(0.f, 0.f);
    float2 F = make_float2(1.f, 1.f);
    #pragma unroll
    for (int i = 0; i < CHUNK; i++) {
        int base = ((t0 + i) * BB + b) * G3 + h;
        float2 z = __half22float2(*(const __half2*)&g_buf[base]);
        float2 f = __half22float2(*(const __half2*)&g_buf[base + HH]);
        c.x = f.x * c.x + (1.0f - f.x) * z.x;  F.x *= f.x;
        c.y = f.y * c.y + (1.0f - f.y) * z.y;  F.y *= f.y;
    }
    *(float2*)&F_buf[chunk * NCH + ch2 * 2]  = F;
    *(float2*)&Gc_buf[chunk * NCH + ch2 * 2] = c;
}

__global__ __launch_bounds__(256) void scan_phaseC_kernel(int layer)
{
    const int ch2 = blockIdx.x * 256 + threadIdx.x;
    const int chunk = blockIdx.y;
    const int b = ch2 >> 8;
    const int h = (ch2 & 255) * 2;
    const int t0 = chunk * CHUNK;

    // chunk prefix from (F, G)
    float2 c = make_float2(0.f, 0.f);
    for (int j = 0; j < chunk; j++) {
        float2 F = *(const float2*)&F_buf[j * NCH + ch2 * 2];
        float2 G = *(const float2*)&Gc_buf[j * NCH + ch2 * 2];
        c.x = F.x * c.x + G.x;
        c.y = F.y * c.y + G.y;
    }

    #pragma unroll
    for (int i = 0; i < CHUNK; i++) {
        int t = t0 + i;
        int base = (t * BB + b) * G3 + h;
        float2 z = __half22float2(*(const __half2*)&g_buf[base]);
        float2 f = __half22float2(*(const __half2*)&g_buf[base + HH]);
        float2 o = __half22float2(*(const __half2*)&g_buf[base + 2 * HH]);
        c.x = f.x * c.x + (1.0f - f.x) * z.x;
        c.y = f.y * c.y + (1.0f - f.y) * z.y;
        float v0 = o.x * c.x, v1 = o.y * c.y;
        int idx = (layer == 0) ? ((t * BB + b) * HH + h) : ((b * TT + t) * HH + h);
        *(__half2*)(A16_buf + idx) = __floats2half2_rn(v0, v1);
    }
}

// ---------------------------------------------------------------------------
// W [K=512, N] -> B [N, K=512] fp16 transpose, 64k x 32n tiles.
// ---------------------------------------------------------------------------
__global__ __launch_bounds__(256) void transpose_f16_kernel(
    const float* __restrict__ W, int N, __half* __restrict__ Bo)
{
    __shared__ float ts[64][33];
    const int n0 = blockIdx.x * 32;
    const int k0 = blockIdx.y * 64;
    const int tid = threadIdx.x;
    const int lane = tid & 31;
    const int w = tid >> 5;

    #pragma unroll
    for (int i = 0; i < 8; i++) {
        int kr = w + i * 8;
        ts[kr][lane] = W[(size_t)(k0 + kr) * N + n0 + lane];
    }
    __syncthreads();
    #pragma unroll
    for (int p = 0; p < 4; p++) {
        int n = w * 4 + p;
        __half2 v = __floats2half2_rn(ts[2 * lane][n], ts[2 * lane + 1][n]);
        *(__half2*)(Bo + (size_t)(n0 + n) * KK + k0 + 2 * lane) = v;
    }
}

// ---------------------------------------------------------------------------
// Unified single-pass fp16 HMMA GEMM: C[M,N] = A[M,512]*B[N,512]^T + bias.
// CTA 128x128, 4 warps of 64x64, K-chunk 64, 3-stage cp.async pipeline.
// ---------------------------------------------------------------------------
#define EPI_STRIDE 132
#define P_LDS_STRIDE 72                       // fp16 elems per row (64 + 8 pad)
#define P_TILE_BYTES (128 * 144)              // 18432
#define P_STAGE (2 * P_TILE_BYTES)            // A + B = 36864
#define TG_SMEM (3 * P_STAGE)                 // 110592 > 128*132*4

template<int NGLOB, int ACT, int OUT16>
__global__ __launch_bounds__(128, 2) void tgemm_f16_kernel(
    const __half* __restrict__ A16, const __half* __restrict__ B16,
    const float* __restrict__ bias, void* __restrict__ Cv)
{
    extern __shared__ __nv_bfloat16 dsm[];
    const uint32_t sbase = smem_u32(dsm);

    const int tid  = threadIdx.x;
    const int wid  = tid >> 5;
    const int lane = tid & 31;
    const int m0 = blockIdx.y * 128;
    const int n0 = blockIdx.x * 128;
    const int wm = (wid & 1) * 64;
    const int wn = (wid >> 1) * 64;

    const int ldRow = tid >> 3;            // 0..15
    const int ldG   = tid & 7;             // 16B chunk within 128B row

    float acc[4][8][4] = {};

    auto issue_loads = [&](int kc, int s) {
        const int k0 = kc * 64;
        const uint32_t sA = sbase + s * P_STAGE;
        const uint32_t sB = sA + P_TILE_BYTES;
        #pragma unroll
        for (int it = 0; it < 8; it++) {
            int row = ldRow + it * 16;
            uint32_t soff = (uint32_t)(row * P_LDS_STRIDE + ldG * 8) * 2;
            cp_async16(sA + soff, A16 + (size_t)(m0 + row) * KK + k0 + ldG * 8);
            cp_async16(sB + soff, B16 + (size_t)(n0 + row) * KK + k0 + ldG * 8);
        }
        cp_commit();
    };

    issue_loads(0, 0);
    issue_loads(1, 1);

    for (int kc = 0; kc < 8; kc++) {
        const int s = kc % 3;
        if (kc + 1 < 8) cp_wait<1>(); else cp_wait<0>();
        __syncthreads();
        if (kc + 2 < 8) issue_loads(kc + 2, (kc + 2) % 3);

        const uint32_t sA = sbase + s * P_STAGE;
        const uint32_t sB = sA + P_TILE_BYTES;

        #pragma unroll
        for (int ks = 0; ks < 4; ks++) {
            const int kb = ks * 32;
            const uint32_t aoff = (uint32_t)((wm + (lane & 15)) * P_LDS_STRIDE) * 2
                                  + kb + ((lane >> 4) * 16);
            const uint32_t boff = (uint32_t)((wn + (lane & 7) + ((lane >> 4) & 1) * 8)
                                  * P_LDS_STRIDE) * 2 + kb + (((lane >> 3) & 1) * 16);

            uint32_t af[4][4];
            uint32_t bf[8][2];
            #pragma unroll
            for (int mt = 0; mt < 4; mt++)
                ldm_x4(af[mt][0], af[mt][1], af[mt][2], af[mt][3],
                       sA + aoff + (uint32_t)(mt * 16 * P_LDS_STRIDE * 2));
            #pragma unroll
            for (int nt2 = 0; nt2 < 4; nt2++) {
                uint32_t r0, r1, r2, r3;
                ldm_x4(r0, r1, r2, r3, sB + boff + (uint32_t)(nt2 * 16 * P_LDS_STRIDE * 2));
                bf[nt2 * 2 + 0][0] = r0; bf[nt2 * 2 + 0][1] = r1;
                bf[nt2 * 2 + 1][0] = r2; bf[nt2 * 2 + 1][1] = r3;
            }

            #pragma unroll
            for (int mt = 0; mt < 4; mt++)
                #pragma unroll
                for (int nt = 0; nt < 8; nt++)
                    mma_f16(acc[mt][nt][0], acc[mt][nt][1], acc[mt][nt][2], acc[mt][nt][3],
                            af[mt][0], af[mt][1], af[mt][2], af[mt][3],
                            bf[nt][0], bf[nt][1]);
        }
    }

    // Epilogue: bias (+ act) -> SMEM fp32 -> coalesced stores (fp16 or fp32)
    __syncthreads();
    float* cs = (float*)dsm;
    const int g = lane >> 2;
    const int cpair = (lane & 3) * 2;
    #pragma unroll
    for (int nt = 0; nt < 8; nt++) {
        int col = wn + nt * 8 + cpair;
        float bv0 = __ldg(bias + n0 + col);
        float bv1 = __ldg(bias + n0 + col + 1);
        #pragma unroll
        for (int mt = 0; mt < 4; mt++) {
            #pragma unroll
            for (int half = 0; half < 2; half++) {
                int row = wm + mt * 16 + g + half * 8;
                float x0 = acc[mt][nt][half * 2 + 0] + bv0;
                float x1 = acc[mt][nt][half * 2 + 1] + bv1;
                if (ACT) {
                    int n = n0 + col;
                    x0 = (n < HH) ? tanhf(x0) : sigmoidf_(x0);
                    x1 = (n + 1 < HH) ? tanhf(x1) : sigmoidf_(x1);
                }
                cs[row * EPI_STRIDE + col]     = x0;
                cs[row * EPI_STRIDE + col + 1] = x1;
            }
        }
    }
    __syncthreads();
    #pragma unroll
    for (int i = 0; i < 32; i++) {
        int row = i * 4 + (tid >> 5);
        int col = (tid & 31) * 4;
        float4 v = *(float4*)&cs[row * EPI_STRIDE + col];
        if (OUT16) {
            __half2 p0 = __floats2half2_rn(v.x, v.y);
            __half2 p1 = __floats2half2_rn(v.z, v.w);
            __half2* dst = (__half2*)((__half*)Cv + (size_t)(m0 + row) * NGLOB + n0 + col);
            dst[0] = p0;
            dst[1] = p1;
        } else {
            *(float4*)((float*)Cv + (size_t)(m0 + row) * NGLOB + n0 + col) = v;
        }
    }
}

// ---------------------------------------------------------------------------
// Launch: weight transposes forked onto a side stream (overlaps gemm1 + scan
// chain in the captured graph); joined before GEMM2 consumes W2^T.
// ---------------------------------------------------------------------------
extern "C" void kernel_launch(void* const* d_in, const int* in_sizes, int n_in,
                              void* d_out, int out_size)
{
    const int*   inputs = (const int*)d_in[0];
    const float* emb    = (const float*)d_in[1];
    const float* W1     = (const float*)d_in[2];
    const float* b1     = (const float*)d_in[3];
    const float* W2     = (const float*)d_in[4];
    const float* b2     = (const float*)d_in[5];
    const float* Wp     = (const float*)d_in[6];
    const float* bp     = (const float*)d_in[7];
    float* out = (float*)d_out;

    cudaFuncSetAttribute(tgemm_f16_kernel<G3, 1, 1>,
                         cudaFuncAttributeMaxDynamicSharedMemorySize, TG_SMEM);
    cudaFuncSetAttribute(tgemm_f16_kernel<VV, 0, 0>,
                         cudaFuncAttributeMaxDynamicSharedMemorySize, TG_SMEM);

    __half *g_gbuf, *g_A16, *g_B216, *g_Bp16;
    cudaGetSymbolAddress((void**)&g_gbuf, g_buf);
    cudaGetSymbolAddress((void**)&g_A16,  A16_buf);
    cudaGetSymbolAddress((void**)&g_B216, B216_buf);
    cudaGetSymbolAddress((void**)&g_Bp16, Bp16_buf);

    // Side stream for weight prep (fork/join via events; capture-legal).
    cudaStream_t s2;
    cudaEvent_t eFork, eJoin;
    cudaStreamCreateWithFlags(&s2, cudaStreamNonBlocking);
    cudaEventCreateWithFlags(&eFork, cudaEventDisableTiming);
    cudaEventCreateWithFlags(&eJoin, cudaEventDisableTiming);

    cudaEventRecord(eFork, 0);
    cudaStreamWaitEvent(s2, eFork, 0);
    transpose_f16_kernel<<<dim3(G3 / 32, KK / 64), 256, 0, s2>>>(W2, G3, g_B216);
    transpose_f16_kernel<<<dim3(VV / 32, KK / 64), 256, 0, s2>>>(Wp, VV, g_Bp16);
    cudaEventRecord(eJoin, s2);

    // Main chain (capture stream): layer 1
    gemm1_kernel<<<dim3(G3 / 64, MM / 64), 256>>>(inputs, emb, W1, b1);
    scan_phaseA_kernel<<<dim3(8, NCHUNK), 256>>>();
    scan_phaseC_kernel<<<dim3(8, NCHUNK), 256>>>(0);

    // Join: GEMM2 needs W2^T (and projection later needs Wp^T)
    cudaStreamWaitEvent(0, eJoin, 0);

    // Layer 2: single-pass fp16 GEMM -> g_buf (fp16) with activations
    tgemm_f16_kernel<G3, 1, 1><<<dim3(G3 / 128, MM / 128), 128, TG_SMEM>>>(
        g_A16, g_B216, b2, g_gbuf);

    // Layer 2 fo-pool -> A16_buf (rows b*T+t)
    scan_phaseA_kernel<<<dim3(8, NCHUNK), 256>>>();
    scan_phaseC_kernel<<<dim3(8, NCHUNK), 256>>>(1);

    // Projection: single-pass fp16 GEMM -> out (fp32)
    tgemm_f16_kernel<VV, 0, 0><<<dim3(VV / 128, MM / 128), 128, TG_SMEM>>>(
        g_A16, g_Bp16, bp, out);

    cudaEventDestroy(eFork);
    cudaEventDestroy(eJoin);
    cudaStreamDestroy(s2);
}

// round 17
// speedup vs baseline: 1.1289x; 1.0203x over previous
#include <cuda_runtime.h>
#include <cuda_bf16.h>
#include <cuda_fp16.h>
#include <math.h>
#include <stdint.h>

// ---------------- dims ----------------
#define BB     8
#define TT     512
#define EE     64
#define HH     512
#define VV     32000
#define G3     1536
#define MM     4096        // B*T
#define KK     512
#define NCH    4096
#define CHUNK  16
#define NCHUNK 32

// ---------------- scratch (static device globals) ----------------
__device__ __half g_buf[MM * G3];               // pre-pool z/f/o, fp16
__device__ float F_buf[NCHUNK * NCH];
__device__ float Gc_buf[NCHUNK * NCH];

__device__ __half A16_buf[MM * KK];             // scan outputs (both layers, fp16)
__device__ __half B216_buf[G3 * KK];            // W2^T fp16
__device__ __half Bp16_buf[(size_t)VV * KK];    // Wp^T fp16

__device__ __forceinline__ float sigmoidf_(float x) {
    return 1.0f / (1.0f + expf(-x));
}

__device__ __forceinline__ uint32_t smem_u32(const void* p) {
    uint32_t a;
    asm("{ .reg .u64 t; cvta.to.shared.u64 t, %1; cvt.u32.u64 %0, t; }" : "=r"(a) : "l"(p));
    return a;
}
__device__ __forceinline__ void cp_async16(uint32_t s, const void* g) {
    asm volatile("cp.async.cg.shared.global [%0], [%1], 16;" :: "r"(s), "l"(g));
}
__device__ __forceinline__ void cp_commit() {
    asm volatile("cp.async.commit_group;");
}
template<int N>
__device__ __forceinline__ void cp_wait() {
    asm volatile("cp.async.wait_group %0;" :: "n"(N));
}
__device__ __forceinline__ void ldm_x4(uint32_t& r0, uint32_t& r1, uint32_t& r2, uint32_t& r3,
                                       uint32_t addr) {
    asm volatile("ldmatrix.sync.aligned.m8n8.x4.shared.b16 {%0,%1,%2,%3}, [%4];"
                 : "=r"(r0), "=r"(r1), "=r"(r2), "=r"(r3) : "r"(addr));
}
__device__ __forceinline__ void mma_f16(float& c0, float& c1, float& c2, float& c3,
                                        uint32_t a0, uint32_t a1, uint32_t a2, uint32_t a3,
                                        uint32_t b0, uint32_t b1) {
    asm volatile("mma.sync.aligned.m16n8k16.row.col.f32.f16.f16.f32 "
                 "{%0,%1,%2,%3}, {%4,%5,%6,%7}, {%8,%9}, {%0,%1,%2,%3};"
                 : "+f"(c0), "+f"(c1), "+f"(c2), "+f"(c3)
                 : "r"(a0), "r"(a1), "r"(a2), "r"(a3), "r"(b0), "r"(b1));
}

// ---------------------------------------------------------------------------
// GEMM1: embed-gather fused small GEMM, K=64. Output fp16 z/f/o.
// ---------------------------------------------------------------------------
__global__ __launch_bounds__(256) void gemm1_kernel(
    const int* __restrict__ inputs, const float* __restrict__ emb,
    const float* __restrict__ W1, const float* __restrict__ b1)
{
    __shared__ float Xs[64 * 65];
    __shared__ float Ws[64 * 64];
    __shared__ int   toks[64];

    const int tid = threadIdx.x;
    const int m0 = blockIdx.y * 64;
    const int n0 = blockIdx.x * 64;

    if (tid < 64) {
        int m = m0 + tid;
        int b = m & 7;
        int t = m >> 3;
        toks[tid] = inputs[b * TT + t];
    }
    __syncthreads();

    #pragma unroll
    for (int i = 0; i < 16; i++) {
        int lin = tid + i * 256;
        int row = lin >> 6, k = lin & 63;
        Xs[row * 65 + k] = emb[toks[row] * EE + k];
    }
    #pragma unroll
    for (int i = 0; i < 16; i++) {
        int lin = tid + i * 256;
        int k = lin >> 6, col = lin & 63;
        Ws[k * 64 + col] = W1[k * G3 + n0 + col];
    }
    __syncthreads();

    const int tx = tid & 15, ty = tid >> 4;
    float acc[4][4] = {};
    #pragma unroll
    for (int k = 0; k < 64; k++) {
        float a[4], w[4];
        #pragma unroll
        for (int i = 0; i < 4; i++) a[i] = Xs[(ty * 4 + i) * 65 + k];
        #pragma unroll
        for (int j = 0; j < 4; j++) w[j] = Ws[k * 64 + tx * 4 + j];
        #pragma unroll
        for (int i = 0; i < 4; i++)
            #pragma unroll
            for (int j = 0; j < 4; j++)
                acc[i][j] = fmaf(a[i], w[j], acc[i][j]);
    }

    #pragma unroll
    for (int i = 0; i < 4; i++) {
        int m = m0 + ty * 4 + i;
        float v[4];
        #pragma unroll
        for (int j = 0; j < 4; j++) {
            int n = n0 + tx * 4 + j;
            float x = acc[i][j] + b1[n];
            v[j] = (n < HH) ? tanhf(x) : sigmoidf_(x);
        }
        __half2 p0 = __floats2half2_rn(v[0], v[1]);
        __half2 p1 = __floats2half2_rn(v[2], v[3]);
        *(__half2*)(g_buf + (size_t)m * G3 + n0 + tx * 4)     = p0;
        *(__half2*)(g_buf + (size_t)m * G3 + n0 + tx * 4 + 2) = p1;
    }
}

// ---------------------------------------------------------------------------
// fo-pool scan, 2 phases, half2 inputs, 2 channels/thread (grid 8x32).
// ---------------------------------------------------------------------------
__global__ __launch_bounds__(256) void scan_phaseA_kernel()
{
    const int ch2 = blockIdx.x * 256 + threadIdx.x;   // 0..2047
    const int chunk = blockIdx.y;
    const int b = ch2 >> 8;
    const int h = (ch2 & 255) * 2;
    const int t0 = chunk * CHUNK;
    float2 c = make_float2(0.f, 0.f);
    float2 F = make_float2(1.f, 1.f);
    #pragma unroll
    for (int i = 0; i < CHUNK; i++) {
        int base = ((t0 + i) * BB + b) * G3 + h;
        float2 z = __half22float2(*(const __half2*)&g_buf[base]);
        float2 f = __half22float2(*(const __half2*)&g_buf[base + HH]);
        c.x = f.x * c.x + (1.0f - f.x) * z.x;  F.x *= f.x;
        c.y = f.y * c.y + (1.0f - f.y) * z.y;  F.y *= f.y;
    }
    *(float2*)&F_buf[chunk * NCH + ch2 * 2]  = F;
    *(float2*)&Gc_buf[chunk * NCH + ch2 * 2] = c;
}

__global__ __launch_bounds__(256) void scan_phaseC_kernel(int layer)
{
    const int ch2 = blockIdx.x * 256 + threadIdx.x;
    const int chunk = blockIdx.y;
    const int b = ch2 >> 8;
    const int h = (ch2 & 255) * 2;
    const int t0 = chunk * CHUNK;

    float2 c = make_float2(0.f, 0.f);
    for (int j = 0; j < chunk; j++) {
        float2 F = *(const float2*)&F_buf[j * NCH + ch2 * 2];
        float2 G = *(const float2*)&Gc_buf[j * NCH + ch2 * 2];
        c.x = F.x * c.x + G.x;
        c.y = F.y * c.y + G.y;
    }

    #pragma unroll
    for (int i = 0; i < CHUNK; i++) {
        int t = t0 + i;
        int base = (t * BB + b) * G3 + h;
        float2 z = __half22float2(*(const __half2*)&g_buf[base]);
        float2 f = __half22float2(*(const __half2*)&g_buf[base + HH]);
        float2 o = __half22float2(*(const __half2*)&g_buf[base + 2 * HH]);
        c.x = f.x * c.x + (1.0f - f.x) * z.x;
        c.y = f.y * c.y + (1.0f - f.y) * z.y;
        float v0 = o.x * c.x, v1 = o.y * c.y;
        int idx = (layer == 0) ? ((t * BB + b) * HH + h) : ((b * TT + t) * HH + h);
        *(__half2*)(A16_buf + idx) = __floats2half2_rn(v0, v1);
    }
}

// ---------------------------------------------------------------------------
// W [K=512, N] -> B [N, K=512] fp16 transpose, 64k x 32n tiles.
// ---------------------------------------------------------------------------
__global__ __launch_bounds__(256) void transpose_f16_kernel(
    const float* __restrict__ W, int N, __half* __restrict__ Bo)
{
    __shared__ float ts[64][33];
    const int n0 = blockIdx.x * 32;
    const int k0 = blockIdx.y * 64;
    const int tid = threadIdx.x;
    const int lane = tid & 31;
    const int w = tid >> 5;

    #pragma unroll
    for (int i = 0; i < 8; i++) {
        int kr = w + i * 8;
        ts[kr][lane] = W[(size_t)(k0 + kr) * N + n0 + lane];
    }
    __syncthreads();
    #pragma unroll
    for (int p = 0; p < 4; p++) {
        int n = w * 4 + p;
        __half2 v = __floats2half2_rn(ts[2 * lane][n], ts[2 * lane + 1][n]);
        *(__half2*)(Bo + (size_t)(n0 + n) * KK + k0 + 2 * lane) = v;
    }
}

#define EPI_STRIDE 132
#define P_LDS_STRIDE 72                       // fp16 elems per row (64 + 8 pad)
#define P_TILE_BYTES (128 * 144)              // 18432
#define P_STAGE (2 * P_TILE_BYTES)            // A + B = 36864
#define TG_SMEM (3 * P_STAGE)                 // 110592 > 128*132*4

// ---------------------------------------------------------------------------
// GEMM2: non-persistent single-pass fp16 GEMM (small, 384 CTAs)
// ---------------------------------------------------------------------------
template<int NGLOB, int ACT, int OUT16>
__global__ __launch_bounds__(128, 2) void tgemm_f16_kernel(
    const __half* __restrict__ A16, const __half* __restrict__ B16,
    const float* __restrict__ bias, void* __restrict__ Cv)
{
    extern __shared__ __nv_bfloat16 dsm[];
    const uint32_t sbase = smem_u32(dsm);

    const int tid  = threadIdx.x;
    const int wid  = tid >> 5;
    const int lane = tid & 31;
    const int m0 = blockIdx.y * 128;
    const int n0 = blockIdx.x * 128;
    const int wm = (wid & 1) * 64;
    const int wn = (wid >> 1) * 64;

    const int ldRow = tid >> 3;
    const int ldG   = tid & 7;

    float acc[4][8][4] = {};

    auto issue_loads = [&](int kc, int s) {
        const int k0 = kc * 64;
        const uint32_t sA = sbase + s * P_STAGE;
        const uint32_t sB = sA + P_TILE_BYTES;
        #pragma unroll
        for (int it = 0; it < 8; it++) {
            int row = ldRow + it * 16;
            uint32_t soff = (uint32_t)(row * P_LDS_STRIDE + ldG * 8) * 2;
            cp_async16(sA + soff, A16 + (size_t)(m0 + row) * KK + k0 + ldG * 8);
            cp_async16(sB + soff, B16 + (size_t)(n0 + row) * KK + k0 + ldG * 8);
        }
        cp_commit();
    };

    issue_loads(0, 0);
    issue_loads(1, 1);

    for (int kc = 0; kc < 8; kc++) {
        const int s = kc % 3;
        if (kc + 1 < 8) cp_wait<1>(); else cp_wait<0>();
        __syncthreads();
        if (kc + 2 < 8) issue_loads(kc + 2, (kc + 2) % 3);

        const uint32_t sA = sbase + s * P_STAGE;
        const uint32_t sB = sA + P_TILE_BYTES;

        #pragma unroll
        for (int ks = 0; ks < 4; ks++) {
            const int kb = ks * 32;
            const uint32_t aoff = (uint32_t)((wm + (lane & 15)) * P_LDS_STRIDE) * 2
                                  + kb + ((lane >> 4) * 16);
            const uint32_t boff = (uint32_t)((wn + (lane & 7) + ((lane >> 4) & 1) * 8)
                                  * P_LDS_STRIDE) * 2 + kb + (((lane >> 3) & 1) * 16);

            uint32_t af[4][4];
            uint32_t bf[8][2];
            #pragma unroll
            for (int mt = 0; mt < 4; mt++)
                ldm_x4(af[mt][0], af[mt][1], af[mt][2], af[mt][3],
                       sA + aoff + (uint32_t)(mt * 16 * P_LDS_STRIDE * 2));
            #pragma unroll
            for (int nt2 = 0; nt2 < 4; nt2++) {
                uint32_t r0, r1, r2, r3;
                ldm_x4(r0, r1, r2, r3, sB + boff + (uint32_t)(nt2 * 16 * P_LDS_STRIDE * 2));
                bf[nt2 * 2 + 0][0] = r0; bf[nt2 * 2 + 0][1] = r1;
                bf[nt2 * 2 + 1][0] = r2; bf[nt2 * 2 + 1][1] = r3;
            }

            #pragma unroll
            for (int mt = 0; mt < 4; mt++)
                #pragma unroll
                for (int nt = 0; nt < 8; nt++)
                    mma_f16(acc[mt][nt][0], acc[mt][nt][1], acc[mt][nt][2], acc[mt][nt][3],
                            af[mt][0], af[mt][1], af[mt][2], af[mt][3],
                            bf[nt][0], bf[nt][1]);
        }
    }

    __syncthreads();
    float* cs = (float*)dsm;
    const int g = lane >> 2;
    const int cpair = (lane & 3) * 2;
    #pragma unroll
    for (int nt = 0; nt < 8; nt++) {
        int col = wn + nt * 8 + cpair;
        float bv0 = __ldg(bias + n0 + col);
        float bv1 = __ldg(bias + n0 + col + 1);
        #pragma unroll
        for (int mt = 0; mt < 4; mt++) {
            #pragma unroll
            for (int half = 0; half < 2; half++) {
                int row = wm + mt * 16 + g + half * 8;
                float x0 = acc[mt][nt][half * 2 + 0] + bv0;
                float x1 = acc[mt][nt][half * 2 + 1] + bv1;
                if (ACT) {
                    int n = n0 + col;
                    x0 = (n < HH) ? tanhf(x0) : sigmoidf_(x0);
                    x1 = (n + 1 < HH) ? tanhf(x1) : sigmoidf_(x1);
                }
                cs[row * EPI_STRIDE + col]     = x0;
                cs[row * EPI_STRIDE + col + 1] = x1;
            }
        }
    }
    __syncthreads();
    #pragma unroll
    for (int i = 0; i < 32; i++) {
        int row = i * 4 + (tid >> 5);
        int col = (tid & 31) * 4;
        float4 v = *(float4*)&cs[row * EPI_STRIDE + col];
        if (OUT16) {
            __half2 p0 = __floats2half2_rn(v.x, v.y);
            __half2 p1 = __floats2half2_rn(v.z, v.w);
            __half2* dst = (__half2*)((__half*)Cv + (size_t)(m0 + row) * NGLOB + n0 + col);
            dst[0] = p0;
            dst[1] = p1;
        } else {
            *(float4*)((float*)Cv + (size_t)(m0 + row) * NGLOB + n0 + col) = v;
        }
    }
}

// ---------------------------------------------------------------------------
// Projection: PERSISTENT single-pass fp16 GEMM. 296 CTAs (2/SM), each walks
// tiles cta, cta+296, ... with a flat cross-tile 3-stage cp.async pipeline
// (empty commit_group past the end keeps group accounting uniform). Epilogue
// is direct float2 stores from acc (no SMEM, no extra barriers) so the next
// tile's prefetch overlaps it.
// ---------------------------------------------------------------------------
#define NTILE_N (VV / 128)          // 250
#define NTILE_M (MM / 128)          // 32
#define NTILES  (NTILE_N * NTILE_M) // 8000
#define NCTAS   296

__global__ __launch_bounds__(128, 2) void tgemm_proj_persist(
    const __half* __restrict__ A16, const __half* __restrict__ B16,
    const float* __restrict__ bias, float* __restrict__ C)
{
    extern __shared__ __nv_bfloat16 dsm[];
    const uint32_t sbase = smem_u32(dsm);

    const int cta  = blockIdx.x;
    const int tid  = threadIdx.x;
    const int wid  = tid >> 5;
    const int lane = tid & 31;
    const int wm = (wid & 1) * 64;
    const int wn = (wid >> 1) * 64;

    const int ldRow = tid >> 3;
    const int ldG   = tid & 7;

    const int nmine = (NTILES - 1 - cta) / NCTAS + 1;
    const int total_chunks = nmine * 8;

    auto issue = [&](int q) {
        int tile = cta + (q >> 3) * NCTAS;
        if (tile < NTILES) {
            int m0 = (tile / NTILE_N) * 128;
            int n0 = (tile % NTILE_N) * 128;
            int k0 = (q & 7) * 64;
            const uint32_t sA = sbase + (q % 3) * P_STAGE;
            const uint32_t sB = sA + P_TILE_BYTES;
            #pragma unroll
            for (int it = 0; it < 8; it++) {
                int row = ldRow + it * 16;
                uint32_t soff = (uint32_t)(row * P_LDS_STRIDE + ldG * 8) * 2;
                cp_async16(sA + soff, A16 + (size_t)(m0 + row) * KK + k0 + ldG * 8);
                cp_async16(sB + soff, B16 + (size_t)(n0 + row) * KK + k0 + ldG * 8);
            }
        }
        cp_commit();
    };

    issue(0);
    issue(1);

    float acc[4][8][4] = {};

    for (int q = 0; q < total_chunks; q++) {
        cp_wait<1>();
        __syncthreads();
        issue(q + 2);

        const int tile = cta + (q >> 3) * NCTAS;
        const int m0 = (tile / NTILE_N) * 128;
        const int n0 = (tile % NTILE_N) * 128;
        const uint32_t sA = sbase + (q % 3) * P_STAGE;
        const uint32_t sB = sA + P_TILE_BYTES;

        #pragma unroll
        for (int ks = 0; ks < 4; ks++) {
            const int kb = ks * 32;
            const uint32_t aoff = (uint32_t)((wm + (lane & 15)) * P_LDS_STRIDE) * 2
                                  + kb + ((lane >> 4) * 16);
            const uint32_t boff = (uint32_t)((wn + (lane & 7) + ((lane >> 4) & 1) * 8)
                                  * P_LDS_STRIDE) * 2 + kb + (((lane >> 3) & 1) * 16);

            uint32_t af[4][4];
            uint32_t bf[8][2];
            #pragma unroll
            for (int mt = 0; mt < 4; mt++)
                ldm_x4(af[mt][0], af[mt][1], af[mt][2], af[mt][3],
                       sA + aoff + (uint32_t)(mt * 16 * P_LDS_STRIDE * 2));
            #pragma unroll
            for (int nt2 = 0; nt2 < 4; nt2++) {
                uint32_t r0, r1, r2, r3;
                ldm_x4(r0, r1, r2, r3, sB + boff + (uint32_t)(nt2 * 16 * P_LDS_STRIDE * 2));
                bf[nt2 * 2 + 0][0] = r0; bf[nt2 * 2 + 0][1] = r1;
                bf[nt2 * 2 + 1][0] = r2; bf[nt2 * 2 + 1][1] = r3;
            }

            #pragma unroll
            for (int mt = 0; mt < 4; mt++)
                #pragma unroll
                for (int nt = 0; nt < 8; nt++)
                    mma_f16(acc[mt][nt][0], acc[mt][nt][1], acc[mt][nt][2], acc[mt][nt][3],
                            af[mt][0], af[mt][1], af[mt][2], af[mt][3],
                            bf[nt][0], bf[nt][1]);
        }

        if ((q & 7) == 7) {
            // Direct-store epilogue: acc + bias -> float2 stores, then reset.
            const int g = lane >> 2;
            const int cpair = (lane & 3) * 2;
            #pragma unroll
            for (int nt = 0; nt < 8; nt++) {
                int n = n0 + wn + nt * 8 + cpair;
                float bv0 = __ldg(bias + n);
                float bv1 = __ldg(bias + n + 1);
                #pragma unroll
                for (int mt = 0; mt < 4; mt++) {
                    #pragma unroll
                    for (int half = 0; half < 2; half++) {
                        int m = m0 + wm + mt * 16 + g + half * 8;
                        float2 v = make_float2(acc[mt][nt][half * 2 + 0] + bv0,
                                               acc[mt][nt][half * 2 + 1] + bv1);
                        *(float2*)(C + (size_t)m * VV + n) = v;
                        acc[mt][nt][half * 2 + 0] = 0.0f;
                        acc[mt][nt][half * 2 + 1] = 0.0f;
                    }
                }
            }
        }
    }
}

// ---------------------------------------------------------------------------
// Launch
// ---------------------------------------------------------------------------
extern "C" void kernel_launch(void* const* d_in, const int* in_sizes, int n_in,
                              void* d_out, int out_size)
{
    const int*   inputs = (const int*)d_in[0];
    const float* emb    = (const float*)d_in[1];
    const float* W1     = (const float*)d_in[2];
    const float* b1     = (const float*)d_in[3];
    const float* W2     = (const float*)d_in[4];
    const float* b2     = (const float*)d_in[5];
    const float* Wp     = (const float*)d_in[6];
    const float* bp     = (const float*)d_in[7];
    float* out = (float*)d_out;

    cudaFuncSetAttribute(tgemm_f16_kernel<G3, 1, 1>,
                         cudaFuncAttributeMaxDynamicSharedMemorySize, TG_SMEM);
    cudaFuncSetAttribute(tgemm_proj_persist,
                         cudaFuncAttributeMaxDynamicSharedMemorySize, TG_SMEM);

    __half *g_gbuf, *g_A16, *g_B216, *g_Bp16;
    cudaGetSymbolAddress((void**)&g_gbuf, g_buf);
    cudaGetSymbolAddress((void**)&g_A16,  A16_buf);
    cudaGetSymbolAddress((void**)&g_B216, B216_buf);
    cudaGetSymbolAddress((void**)&g_Bp16, Bp16_buf);

    // Side stream for weight prep (fork/join via events; capture-legal).
    cudaStream_t s2;
    cudaEvent_t eFork, eJoin;
    cudaStreamCreateWithFlags(&s2, cudaStreamNonBlocking);
    cudaEventCreateWithFlags(&eFork, cudaEventDisableTiming);
    cudaEventCreateWithFlags(&eJoin, cudaEventDisableTiming);

    cudaEventRecord(eFork, 0);
    cudaStreamWaitEvent(s2, eFork, 0);
    transpose_f16_kernel<<<dim3(G3 / 32, KK / 64), 256, 0, s2>>>(W2, G3, g_B216);
    transpose_f16_kernel<<<dim3(VV / 32, KK / 64), 256, 0, s2>>>(Wp, VV, g_Bp16);
    cudaEventRecord(eJoin, s2);

    // Main chain: layer 1
    gemm1_kernel<<<dim3(G3 / 64, MM / 64), 256>>>(inputs, emb, W1, b1);
    scan_phaseA_kernel<<<dim3(8, NCHUNK), 256>>>();
    scan_phaseC_kernel<<<dim3(8, NCHUNK), 256>>>(0);

    // Join: GEMM2 needs W2^T (projection later needs Wp^T)
    cudaStreamWaitEvent(0, eJoin, 0);

    // Layer 2: single-pass fp16 GEMM -> g_buf (fp16) with activations
    tgemm_f16_kernel<G3, 1, 1><<<dim3(G3 / 128, MM / 128), 128, TG_SMEM>>>(
        g_A16, g_B216, b2, g_gbuf);

    // Layer 2 fo-pool -> A16_buf (rows b*T+t)
    scan_phaseA_kernel<<<dim3(8, NCHUNK), 256>>>();
    scan_phaseC_kernel<<<dim3(8, NCHUNK), 256>>>(1);

    // Projection: persistent fp16 GEMM -> out (fp32)
    tgemm_proj_persist<<<NCTAS, 128, TG_SMEM>>>(g_A16, g_Bp16, bp, out);

    cudaEventDestroy(eFork);
    cudaEventDestroy(eJoin);
    cudaStreamDestroy(s2);
}